// round 7
// baseline (speedup 1.0000x reference)
#include <cuda_runtime.h>
#include <math.h>

#define BATCH 4
#define SEQ   512
#define HD    768
#define DD    24
#define MMDIM 96
#define OO    768
#define ROWS  (BATCH*SEQ)       // 2048
#define XCOLS (3*HD)            // 2304

typedef unsigned long long ull;

// ---------------- scratch (no allocations allowed) ----------------
__device__ float g_Zj[ROWS*DD];
__device__ float g_Zi[ROWS*DD];
__device__ float g_tjb[ROWS*MMDIM];
__device__ float g_ti[ROWS*MMDIM];
__device__ float g_probs[(long)BATCH*SEQ*SEQ];
__device__ float g_ctx[(long)ROWS*HD];
__device__ float g_mhid[(long)ROWS*OO];

// ---------------- packed f32x2 helpers ----------------
__device__ __forceinline__ ull pk2(float x) {
    ull r; asm("mov.b64 %0, {%1, %1};" : "=l"(r) : "f"(x)); return r;
}
__device__ __forceinline__ void fma2(ull &d, ull a, ull b) {
    asm("fma.rn.f32x2 %0, %1, %2, %0;" : "+l"(d) : "l"(a), "l"(b));
}
__device__ __forceinline__ void add2(ull &d, ull a) {
    asm("add.rn.f32x2 %0, %0, %1;" : "+l"(d) : "l"(a));
}
__device__ __forceinline__ float2 up2(ull v) {
    float2 r; asm("mov.b64 {%0, %1}, %2;" : "=f"(r.x), "=f"(r.y) : "l"(v)); return r;
}

// ---------------- small generic SGEMM, z-batched over pointer pairs ----------------
__global__ __launch_bounds__(256)
void sgemm_small2(const float* __restrict__ A0, const float* __restrict__ B0,
                  float* __restrict__ C0, const float* __restrict__ bias0,
                  const float* __restrict__ A1, const float* __restrict__ B1,
                  float* __restrict__ C1, const float* __restrict__ bias1,
                  int M, int N, int K, int lda, int ldb, int ldc)
{
    __shared__ float As[16][64];
    __shared__ float Bs[16][64];
    const float* A = blockIdx.z ? A1 : A0;
    const float* B = blockIdx.z ? B1 : B0;
    float*       C = blockIdx.z ? C1 : C0;
    const float* bias = blockIdx.z ? bias1 : bias0;

    const int tid = threadIdx.x;
    const int tx = tid & 15, ty = tid >> 4;
    const int row0 = blockIdx.y * 64;
    const int col0 = blockIdx.x * 64;

    float acc[4][4] = {};
    for (int k0 = 0; k0 < K; k0 += 16) {
        #pragma unroll
        for (int u = 0; u < 4; ++u) {
            int t = tid + u * 256;
            int r = t >> 4, kk = t & 15;
            int gr = row0 + r, gk = k0 + kk;
            float v = 0.f;
            if (gr < M && gk < K) v = A[(long)gr * lda + gk];
            As[kk][r] = v;
        }
        #pragma unroll
        for (int u = 0; u < 4; ++u) {
            int t = tid + u * 256;
            int kk = t >> 6, n = t & 63;
            int gk = k0 + kk, gn = col0 + n;
            float v = 0.f;
            if (gk < K && gn < N) v = B[(long)gk * ldb + gn];
            Bs[kk][n] = v;
        }
        __syncthreads();
        #pragma unroll
        for (int kk = 0; kk < 16; ++kk) {
            float4 a4 = *(const float4*)&As[kk][ty * 4];
            float4 b4 = *(const float4*)&Bs[kk][tx * 4];
            float a[4] = {a4.x, a4.y, a4.z, a4.w};
            float b[4] = {b4.x, b4.y, b4.z, b4.w};
            #pragma unroll
            for (int i = 0; i < 4; ++i)
                #pragma unroll
                for (int j = 0; j < 4; ++j)
                    acc[i][j] = fmaf(a[i], b[j], acc[i][j]);
        }
        __syncthreads();
    }
    #pragma unroll
    for (int i = 0; i < 4; ++i) {
        int r = row0 + ty * 4 + i;
        if (r >= M) continue;
        #pragma unroll
        for (int j = 0; j < 4; ++j) {
            int c = col0 + tx * 4 + j;
            if (c >= N) continue;
            float v = acc[i][j];
            if (bias) v += bias[c];
            C[(long)r * ldc + c] = v;
        }
    }
}

// ---------------- gemmks4: 64x64 tile, 256 threads, intra-block split-K x4 ----------------
// Each 64-thread k-group runs a balanced 8x8 microtile (rows {ty*4, ty*4+32},
// cols {tx*4, tx*4+32}) over a quarter of each 32-k tile. All fragment LDS.128
// are bank-conflict-free. Tree reduction via smem reuse, packed f32x2 adds.
// Exact-multiple dims (K % 32 == 0), unguarded.
// AMODE 0: plain A. AMODE 1: A = [ctx | Hj | ctx*Hj] generated on the fly.
template<int AMODE, bool BIAS, bool RELU, bool SCALE>
__global__ __launch_bounds__(256)
void gemmks4(const float* __restrict__ A, const float* __restrict__ B,
             float* __restrict__ C, int K, int lda, int ldb, int ldc,
             const float* __restrict__ bias, const float* __restrict__ alpha_ptr,
             long sA, long sB, long sC,
             const float* __restrict__ Actx, const float* __restrict__ Ahj)
{
    __shared__ float As[2][32][68];   // [buf][k][row]   (17408 B)
    __shared__ float Bs[2][32][68];   // [buf][k][col]

    const int bz = blockIdx.z;
    if (AMODE == 0) A += (long)bz * sA;
    B += (long)bz * sB;  C += (long)bz * sC;

    const int tid = threadIdx.x;
    const int kg = tid >> 6;           // k-group 0..3
    const int lt = tid & 63;
    const int tx = lt & 7;             // 8 col groups
    const int ty = lt >> 3;            // 8 row groups
    const int row0 = blockIdx.y * 64;
    const int col0 = blockIdx.x * 64;

    ull acc[8][4];
    #pragma unroll
    for (int i = 0; i < 8; ++i)
        #pragma unroll
        for (int j = 0; j < 4; ++j) acc[i][j] = 0ull;

    float4 pa[2], pb[2];

    // A tile: 64 rows x 32 k = 512 float4 (2 passes of 256 threads)
    auto loadA = [&](int kt) {
        #pragma unroll
        for (int u = 0; u < 2; ++u) {
            int lin = tid + u * 256;
            int r = lin >> 3, kc = lin & 7;
            int gk = kt + kc * 4;
            if (AMODE == 0) {
                pa[u] = *(const float4*)&A[(long)(row0 + r) * lda + gk];
            } else {
                long ridx = (long)(row0 + r) * HD;
                if (gk < HD) {
                    pa[u] = *(const float4*)&Actx[ridx + gk];
                } else if (gk < 2 * HD) {
                    pa[u] = *(const float4*)&Ahj[ridx + gk - HD];
                } else {
                    float4 c4 = *(const float4*)&Actx[ridx + gk - 2 * HD];
                    float4 h4 = *(const float4*)&Ahj[ridx + gk - 2 * HD];
                    pa[u].x = c4.x * h4.x; pa[u].y = c4.y * h4.y;
                    pa[u].z = c4.z * h4.z; pa[u].w = c4.w * h4.w;
                }
            }
        }
    };
    // B tile: 32 k x 64 n = 512 float4
    auto loadB = [&](int kt) {
        #pragma unroll
        for (int u = 0; u < 2; ++u) {
            int lin = tid + u * 256;
            int bkr = lin >> 4, bn4 = lin & 15;
            pb[u] = *(const float4*)&B[(long)(kt + bkr) * ldb + col0 + bn4 * 4];
        }
    };
    auto storeTiles = [&](int buf) {
        #pragma unroll
        for (int u = 0; u < 2; ++u) {
            int lin = tid + u * 256;
            int r = lin >> 3, kc = lin & 7;
            As[buf][kc * 4 + 0][r] = pa[u].x;
            As[buf][kc * 4 + 1][r] = pa[u].y;
            As[buf][kc * 4 + 2][r] = pa[u].z;
            As[buf][kc * 4 + 3][r] = pa[u].w;
            int bkr = lin >> 4, bn4 = lin & 15;
            *(float4*)&Bs[buf][bkr][bn4 * 4] = pb[u];
        }
    };

    loadA(0); loadB(0);
    storeTiles(0);
    __syncthreads();

    int cur = 0;
    for (int kt = 0; kt < K; kt += 32) {
        const bool more = (kt + 32) < K;
        if (more) { loadA(kt + 32); loadB(kt + 32); }

        #pragma unroll
        for (int kk = 0; kk < 8; ++kk) {
            const int k = kg * 8 + kk;
            float4 a0 = *(const float4*)&As[cur][k][ty * 4];
            float4 a1 = *(const float4*)&As[cur][k][ty * 4 + 32];
            ulonglong2 b0 = *(const ulonglong2*)&Bs[cur][k][tx * 4];
            ulonglong2 b1 = *(const ulonglong2*)&Bs[cur][k][tx * 4 + 32];
            ull ap[8];
            ap[0] = pk2(a0.x); ap[1] = pk2(a0.y); ap[2] = pk2(a0.z); ap[3] = pk2(a0.w);
            ap[4] = pk2(a1.x); ap[5] = pk2(a1.y); ap[6] = pk2(a1.z); ap[7] = pk2(a1.w);
            #pragma unroll
            for (int i = 0; i < 8; ++i) {
                fma2(acc[i][0], ap[i], b0.x);
                fma2(acc[i][1], ap[i], b0.y);
                fma2(acc[i][2], ap[i], b1.x);
                fma2(acc[i][3], ap[i], b1.y);
            }
        }
        if (more) {
            storeTiles(cur ^ 1);
        }
        __syncthreads();
        if (more) cur ^= 1;
    }

    // ---- cross-kg tree reduction (reuse As/Bs; 2048 ull each, need 2048) ----
    ull* bufA = (ull*)&As[0][0][0];
    ull* bufB = (ull*)&Bs[0][0][0];
    if (kg == 1) {
        #pragma unroll
        for (int i = 0; i < 8; ++i)
            #pragma unroll
            for (int j = 0; j < 4; ++j) bufA[(i * 4 + j) * 64 + lt] = acc[i][j];
    }
    if (kg == 3) {
        #pragma unroll
        for (int i = 0; i < 8; ++i)
            #pragma unroll
            for (int j = 0; j < 4; ++j) bufB[(i * 4 + j) * 64 + lt] = acc[i][j];
    }
    __syncthreads();
    if (kg == 0) {
        #pragma unroll
        for (int i = 0; i < 8; ++i)
            #pragma unroll
            for (int j = 0; j < 4; ++j) add2(acc[i][j], bufA[(i * 4 + j) * 64 + lt]);
    }
    if (kg == 2) {
        #pragma unroll
        for (int i = 0; i < 8; ++i)
            #pragma unroll
            for (int j = 0; j < 4; ++j) add2(acc[i][j], bufB[(i * 4 + j) * 64 + lt]);
    }
    __syncthreads();
    if (kg == 2) {
        #pragma unroll
        for (int i = 0; i < 8; ++i)
            #pragma unroll
            for (int j = 0; j < 4; ++j) bufA[(i * 4 + j) * 64 + lt] = acc[i][j];
    }
    __syncthreads();
    if (kg != 0) return;
    #pragma unroll
    for (int i = 0; i < 8; ++i)
        #pragma unroll
        for (int j = 0; j < 4; ++j) add2(acc[i][j], bufA[(i * 4 + j) * 64 + lt]);

    float alpha = 1.f;
    if (SCALE) alpha = *alpha_ptr;
    float4 bv0, bv1;
    if (BIAS) {
        bv0 = *(const float4*)&bias[col0 + tx * 4];
        bv1 = *(const float4*)&bias[col0 + tx * 4 + 32];
    }

    #pragma unroll
    for (int i = 0; i < 8; ++i) {
        int r = row0 + ty * 4 + ((i < 4) ? i : (32 + i - 4));
        #pragma unroll
        for (int half = 0; half < 2; ++half) {
            int c = col0 + tx * 4 + half * 32;
            float2 p0 = up2(acc[i][half * 2 + 0]);
            float2 p1 = up2(acc[i][half * 2 + 1]);
            float4 v = make_float4(p0.x, p0.y, p1.x, p1.y);
            if (BIAS) {
                float4 bv = half ? bv1 : bv0;
                v.x += bv.x; v.y += bv.y; v.z += bv.z; v.w += bv.w;
            }
            if (RELU) {
                v.x = fmaxf(v.x, 0.f); v.y = fmaxf(v.y, 0.f);
                v.z = fmaxf(v.z, 0.f); v.w = fmaxf(v.w, 0.f);
            }
            v.x *= alpha; v.y *= alpha; v.z *= alpha; v.w *= alpha;
            *(float4*)&C[(long)r * ldc + c] = v;
        }
    }
}

// ---------------- fused pairwise logits + softmax (FFMA2) ----------------
// One block (128 thr) per p-row. q-tile 128, microtile 8q x 12m, K=48 in 2 phases of 24.
__global__ __launch_bounds__(128)
void pairwise_kernel(const float* __restrict__ Zj, const float* __restrict__ Zi,
                     const float* __restrict__ tjb, const float* __restrict__ ti,
                     const float* __restrict__ Ws1, const float* __restrict__ ws2,
                     const float* __restrict__ bs2, const int* __restrict__ attn_mask,
                     float* __restrict__ probs)
{
    __shared__ float Wc_s[48][96];
    __shared__ float Gs[24][128];
    __shared__ float Zis[128][25];
    __shared__ float logits_s[512];
    __shared__ float Zjp_s[24];
    __shared__ float tjb_s[96];
    __shared__ float ws2_s[96];
    __shared__ float red_s[8];

    const int tid = threadIdx.x;
    const int tx = tid & 7;
    const int ty = tid >> 3;
    const int pg = blockIdx.x;
    const int b = pg >> 9;

    for (int idx = tid; idx < 48 * 96; idx += 128)
        (&Wc_s[0][0])[idx] = Ws1[48 * 96 + idx];
    if (tid < 24) Zjp_s[tid] = Zj[pg * 24 + tid];
    if (tid < 96) { tjb_s[tid] = tjb[pg * 96 + tid]; ws2_s[tid] = ws2[tid]; }
    __syncthreads();

    #pragma unroll 1
    for (int qt = 0; qt < 4; ++qt) {
        const int q0 = qt * 128;
        for (int idx = tid; idx < 128 * 24; idx += 128) {
            int q = idx / 24, d = idx - q * 24;
            Zis[q][d] = Zi[((long)(b * 512 + q0 + q)) * 24 + d];
        }
        __syncthreads();

        ull acc[8][6];
        #pragma unroll
        for (int i = 0; i < 8; ++i)
            #pragma unroll
            for (int j = 0; j < 6; ++j) acc[i][j] = 0ull;

        #pragma unroll 1
        for (int ph = 0; ph < 2; ++ph) {
            for (int idx = tid; idx < 24 * 128; idx += 128) {
                int k = idx >> 7, q = idx & 127;
                float zj = Zjp_s[k], zi = Zis[q][k];
                Gs[k][q] = ph ? fabsf(zj - zi) : zj * zi;
            }
            __syncthreads();
            const int kbase = ph * 24;
            #pragma unroll
            for (int k = 0; k < 24; ++k) {
                float4 g0 = *(const float4*)&Gs[k][ty * 8];
                float4 g1 = *(const float4*)&Gs[k][ty * 8 + 4];
                ulonglong2 w0 = *(const ulonglong2*)&Wc_s[kbase + k][tx * 12];
                ulonglong2 w1 = *(const ulonglong2*)&Wc_s[kbase + k][tx * 12 + 4];
                ulonglong2 w2 = *(const ulonglong2*)&Wc_s[kbase + k][tx * 12 + 8];
                ull gp[8];
                gp[0] = pk2(g0.x); gp[1] = pk2(g0.y); gp[2] = pk2(g0.z); gp[3] = pk2(g0.w);
                gp[4] = pk2(g1.x); gp[5] = pk2(g1.y); gp[6] = pk2(g1.z); gp[7] = pk2(g1.w);
                #pragma unroll
                for (int i = 0; i < 8; ++i) {
                    fma2(acc[i][0], gp[i], w0.x);
                    fma2(acc[i][1], gp[i], w0.y);
                    fma2(acc[i][2], gp[i], w1.x);
                    fma2(acc[i][3], gp[i], w1.y);
                    fma2(acc[i][4], gp[i], w2.x);
                    fma2(acc[i][5], gp[i], w2.y);
                }
            }
            __syncthreads();
        }

        #pragma unroll
        for (int i = 0; i < 8; ++i) {
            int q = ty * 8 + i;
            const float4* tirow = (const float4*)&ti[((long)(b * 512 + q0 + q)) * 96 + tx * 12];
            float4 t0 = tirow[0], t1 = tirow[1], t2 = tirow[2];
            float tv[12] = {t0.x, t0.y, t0.z, t0.w, t1.x, t1.y, t1.z, t1.w,
                            t2.x, t2.y, t2.z, t2.w};
            float s = 0.f;
            #pragma unroll
            for (int j = 0; j < 6; ++j) {
                int m = tx * 12 + 2 * j;
                float2 a = up2(acc[i][j]);
                float h0 = fmaxf(a.x + tjb_s[m] + tv[2 * j], 0.f);
                float h1 = fmaxf(a.y + tjb_s[m + 1] + tv[2 * j + 1], 0.f);
                s = fmaf(h0, ws2_s[m], s);
                s = fmaf(h1, ws2_s[m + 1], s);
            }
            s += __shfl_xor_sync(0xffffffffu, s, 1);
            s += __shfl_xor_sync(0xffffffffu, s, 2);
            s += __shfl_xor_sync(0xffffffffu, s, 4);
            if (tx == 0) logits_s[q0 + q] = s;
        }
    }
    __syncthreads();

    const float bs2v = *bs2;
    #pragma unroll
    for (int q = tid; q < 512; q += 128) {
        float mv = (float)attn_mask[b * 512 + q];
        logits_s[q] += bs2v + (1.f - mv) * (-3.402823466e38f);
    }
    __syncthreads();

    const int wid = tid >> 5, lane = tid & 31;
    float lmax = -INFINITY;
    #pragma unroll
    for (int q = tid; q < 512; q += 128) lmax = fmaxf(lmax, logits_s[q]);
    #pragma unroll
    for (int o = 16; o > 0; o >>= 1) lmax = fmaxf(lmax, __shfl_xor_sync(0xffffffffu, lmax, o));
    if (lane == 0) red_s[wid] = lmax;
    __syncthreads();
    lmax = fmaxf(fmaxf(red_s[0], red_s[1]), fmaxf(red_s[2], red_s[3]));

    float lsum = 0.f;
    float ev[4];
    #pragma unroll
    for (int u = 0; u < 4; ++u) {
        int q = tid + u * 128;
        ev[u] = expf(logits_s[q] - lmax);
        lsum += ev[u];
    }
    #pragma unroll
    for (int o = 16; o > 0; o >>= 1) lsum += __shfl_xor_sync(0xffffffffu, lsum, o);
    if (lane == 0) red_s[4 + wid] = lsum;
    __syncthreads();
    const float inv = 1.f / (red_s[4] + red_s[5] + red_s[6] + red_s[7]);
    #pragma unroll
    for (int u = 0; u < 4; ++u) {
        int q = tid + u * 128;
        probs[(long)pg * 512 + q] = ev[u] * inv;
    }
}

// ---------------- launch ----------------
extern "C" void kernel_launch(void* const* d_in, const int* in_sizes, int n_in,
                              void* d_out, int out_size)
{
    const float* Hj   = (const float*)d_in[0];
    const float* Hi   = (const float*)d_in[1];
    const float* Wpj  = (const float*)d_in[2];
    const float* Wpi  = (const float*)d_in[3];
    const float* Ws1  = (const float*)d_in[4];
    const float* bs1  = (const float*)d_in[5];
    const float* ws2  = (const float*)d_in[6];
    const float* bs2  = (const float*)d_in[7];
    const float* Wv1  = (const float*)d_in[8];
    const float* bv1  = (const float*)d_in[9];
    const float* Wv2  = (const float*)d_in[10];
    const float* bv2  = (const float*)d_in[11];
    const float* alpha= (const float*)d_in[12];
    const int*   mask = (const int*)d_in[13];
    float* out = (float*)d_out;

    float *Zj, *Zi, *tjb, *ti, *probs, *ctx, *mhid;
    cudaGetSymbolAddress((void**)&Zj, g_Zj);
    cudaGetSymbolAddress((void**)&Zi, g_Zi);
    cudaGetSymbolAddress((void**)&tjb, g_tjb);
    cudaGetSymbolAddress((void**)&ti, g_ti);
    cudaGetSymbolAddress((void**)&probs, g_probs);
    cudaGetSymbolAddress((void**)&ctx, g_ctx);
    cudaGetSymbolAddress((void**)&mhid, g_mhid);

    // Zj = H_j @ Wpj ; Zi = H_i @ Wpi   (2048 x 24, K=768), batched
    sgemm_small2<<<dim3(1, ROWS/64, 2), 256>>>(
        Hj, Wpj, Zj, nullptr, Hi, Wpi, Zi, nullptr,
        ROWS, DD, HD, HD, DD, DD);

    // tjb = Zj @ Ws1[0:24] + bs1 ; ti = Zi @ Ws1[24:48]   (2048 x 96, K=24), batched
    sgemm_small2<<<dim3(2, ROWS/64, 2), 256>>>(
        Zj, Ws1, tjb, bs1, Zi, Ws1 + DD * MMDIM, ti, nullptr,
        ROWS, MMDIM, DD, DD, MMDIM, MMDIM);

    // fused pairwise logits + softmax -> probs
    pairwise_kernel<<<ROWS, 128>>>(Zj, Zi, tjb, ti, Ws1, ws2, bs2, mask, probs);

    // ctx = probs @ H_i   (batched 4x: 512 x 768, K=512)
    gemmks4<0,false,false,false><<<dim3(HD/64, SEQ/64, BATCH), 256>>>(
        probs, Hi, ctx, SEQ, SEQ, HD, HD, nullptr, nullptr,
        (long)SEQ*SEQ, (long)SEQ*HD, (long)SEQ*HD, nullptr, nullptr);

    // mhid = relu([ctx|Hj|ctx*Hj] @ Wv1 + bv1)   (2048 x 768, K=2304; X fused)
    gemmks4<1,true,true,false><<<dim3(OO/64, ROWS/64, 1), 256>>>(
        nullptr, Wv1, mhid, XCOLS, 0, OO, OO, bv1, nullptr,
        0, 0, 0, ctx, Hj);

    // out = alpha * (mhid @ Wv2 + bv2)   (2048 x 768, K=768)
    gemmks4<0,true,false,true><<<dim3(HD/64, ROWS/64, 1), 256>>>(
        mhid, Wv2, out, OO, OO, HD, HD, bv2, alpha,
        0, 0, 0, nullptr, nullptr);
}

// round 8
// speedup vs baseline: 1.5400x; 1.5400x over previous
#include <cuda_runtime.h>
#include <math.h>

#define BATCH 4
#define SEQ   512
#define HD    768
#define DD    24
#define MMDIM 96
#define OO    768
#define ROWS  (BATCH*SEQ)       // 2048
#define XCOLS (3*HD)            // 2304

typedef unsigned long long ull;

// ---------------- scratch (no allocations allowed) ----------------
__device__ float g_Zj[ROWS*DD];
__device__ float g_Zi[ROWS*DD];
__device__ float g_tjb[ROWS*MMDIM];
__device__ float g_ti[ROWS*MMDIM];
__device__ float g_probs[(long)BATCH*SEQ*SEQ];
__device__ float g_ctx[(long)ROWS*HD];
__device__ float g_mhid[(long)ROWS*OO];

// ---------------- packed f32x2 helpers ----------------
__device__ __forceinline__ ull pk2(float x) {
    ull r; asm("mov.b64 %0, {%1, %1};" : "=l"(r) : "f"(x)); return r;
}
__device__ __forceinline__ void fma2(ull &d, ull a, ull b) {
    asm("fma.rn.f32x2 %0, %1, %2, %0;" : "+l"(d) : "l"(a), "l"(b));
}
__device__ __forceinline__ float2 up2(ull v) {
    float2 r; asm("mov.b64 {%0, %1}, %2;" : "=f"(r.x), "=f"(r.y) : "l"(v)); return r;
}

// ---------------- small generic SGEMM, z-batched over pointer pairs ----------------
__global__ __launch_bounds__(256)
void sgemm_small2(const float* __restrict__ A0, const float* __restrict__ B0,
                  float* __restrict__ C0, const float* __restrict__ bias0,
                  const float* __restrict__ A1, const float* __restrict__ B1,
                  float* __restrict__ C1, const float* __restrict__ bias1,
                  int M, int N, int K, int lda, int ldb, int ldc)
{
    __shared__ float As[16][64];
    __shared__ float Bs[16][64];
    const float* A = blockIdx.z ? A1 : A0;
    const float* B = blockIdx.z ? B1 : B0;
    float*       C = blockIdx.z ? C1 : C0;
    const float* bias = blockIdx.z ? bias1 : bias0;

    const int tid = threadIdx.x;
    const int tx = tid & 15, ty = tid >> 4;
    const int row0 = blockIdx.y * 64;
    const int col0 = blockIdx.x * 64;

    float acc[4][4] = {};
    for (int k0 = 0; k0 < K; k0 += 16) {
        #pragma unroll
        for (int u = 0; u < 4; ++u) {
            int t = tid + u * 256;
            int r = t >> 4, kk = t & 15;
            int gr = row0 + r, gk = k0 + kk;
            float v = 0.f;
            if (gr < M && gk < K) v = A[(long)gr * lda + gk];
            As[kk][r] = v;
        }
        #pragma unroll
        for (int u = 0; u < 4; ++u) {
            int t = tid + u * 256;
            int kk = t >> 6, n = t & 63;
            int gk = k0 + kk, gn = col0 + n;
            float v = 0.f;
            if (gk < K && gn < N) v = B[(long)gk * ldb + gn];
            Bs[kk][n] = v;
        }
        __syncthreads();
        #pragma unroll
        for (int kk = 0; kk < 16; ++kk) {
            float4 a4 = *(const float4*)&As[kk][ty * 4];
            float4 b4 = *(const float4*)&Bs[kk][tx * 4];
            float a[4] = {a4.x, a4.y, a4.z, a4.w};
            float b[4] = {b4.x, b4.y, b4.z, b4.w};
            #pragma unroll
            for (int i = 0; i < 4; ++i)
                #pragma unroll
                for (int j = 0; j < 4; ++j)
                    acc[i][j] = fmaf(a[i], b[j], acc[i][j]);
        }
        __syncthreads();
    }
    #pragma unroll
    for (int i = 0; i < 4; ++i) {
        int r = row0 + ty * 4 + i;
        if (r >= M) continue;
        #pragma unroll
        for (int j = 0; j < 4; ++j) {
            int c = col0 + tx * 4 + j;
            if (c >= N) continue;
            float v = acc[i][j];
            if (bias) v += bias[c];
            C[(long)r * ldc + c] = v;
        }
    }
}

// ---------------- gemmks: 64x64 tile, 256 threads, intra-block split-K x2 (R6) ----------------
template<int AMODE, bool BIAS, bool RELU, bool SCALE>
__global__ __launch_bounds__(256)
void gemmks(const float* __restrict__ A, const float* __restrict__ B,
            float* __restrict__ C, int K, int lda, int ldb, int ldc,
            const float* __restrict__ bias, const float* __restrict__ alpha_ptr,
            long sA, long sB, long sC,
            const float* __restrict__ Actx, const float* __restrict__ Ahj)
{
    __shared__ float As[2][32][68];
    __shared__ float Bs[2][32][68];

    const int bz = blockIdx.z;
    if (AMODE == 0) A += (long)bz * sA;
    B += (long)bz * sB;  C += (long)bz * sC;

    const int tid = threadIdx.x;
    const int kg = tid >> 7;
    const int lt = tid & 127;
    const int tx = lt & 15;
    const int ty = lt >> 4;
    const int row0 = blockIdx.y * 64;
    const int col0 = blockIdx.x * 64;

    ull acc[8][2];
    #pragma unroll
    for (int i = 0; i < 8; ++i) { acc[i][0] = 0ull; acc[i][1] = 0ull; }

    float4 pa[2], pb[2];

    auto loadA = [&](int kt) {
        #pragma unroll
        for (int u = 0; u < 2; ++u) {
            int lin = tid + u * 256;
            int r = lin >> 3, kc = lin & 7;
            int gk = kt + kc * 4;
            if (AMODE == 0) {
                pa[u] = *(const float4*)&A[(long)(row0 + r) * lda + gk];
            } else {
                long ridx = (long)(row0 + r) * HD;
                if (gk < HD) {
                    pa[u] = *(const float4*)&Actx[ridx + gk];
                } else if (gk < 2 * HD) {
                    pa[u] = *(const float4*)&Ahj[ridx + gk - HD];
                } else {
                    float4 c4 = *(const float4*)&Actx[ridx + gk - 2 * HD];
                    float4 h4 = *(const float4*)&Ahj[ridx + gk - 2 * HD];
                    pa[u].x = c4.x * h4.x; pa[u].y = c4.y * h4.y;
                    pa[u].z = c4.z * h4.z; pa[u].w = c4.w * h4.w;
                }
            }
        }
    };
    auto loadB = [&](int kt) {
        #pragma unroll
        for (int u = 0; u < 2; ++u) {
            int lin = tid + u * 256;
            int bkr = lin >> 4, bn4 = lin & 15;
            pb[u] = *(const float4*)&B[(long)(kt + bkr) * ldb + col0 + bn4 * 4];
        }
    };
    auto storeTiles = [&](int buf) {
        #pragma unroll
        for (int u = 0; u < 2; ++u) {
            int lin = tid + u * 256;
            int r = lin >> 3, kc = lin & 7;
            As[buf][kc * 4 + 0][r] = pa[u].x;
            As[buf][kc * 4 + 1][r] = pa[u].y;
            As[buf][kc * 4 + 2][r] = pa[u].z;
            As[buf][kc * 4 + 3][r] = pa[u].w;
            int bkr = lin >> 4, bn4 = lin & 15;
            *(float4*)&Bs[buf][bkr][bn4 * 4] = pb[u];
        }
    };

    loadA(0); loadB(0);
    storeTiles(0);
    __syncthreads();

    int cur = 0;
    for (int kt = 0; kt < K; kt += 32) {
        const bool more = (kt + 32) < K;
        if (more) { loadA(kt + 32); loadB(kt + 32); }

        #pragma unroll
        for (int kk = 0; kk < 16; ++kk) {
            const int k = kg * 16 + kk;
            float4 a0 = *(const float4*)&As[cur][k][ty * 8];
            float4 a1 = *(const float4*)&As[cur][k][ty * 8 + 4];
            ulonglong2 bl = *(const ulonglong2*)&Bs[cur][k][tx * 4];
            ull ap[8];
            ap[0] = pk2(a0.x); ap[1] = pk2(a0.y); ap[2] = pk2(a0.z); ap[3] = pk2(a0.w);
            ap[4] = pk2(a1.x); ap[5] = pk2(a1.y); ap[6] = pk2(a1.z); ap[7] = pk2(a1.w);
            #pragma unroll
            for (int i = 0; i < 8; ++i) {
                fma2(acc[i][0], ap[i], bl.x);
                fma2(acc[i][1], ap[i], bl.y);
            }
        }
        if (more) {
            storeTiles(cur ^ 1);
        }
        __syncthreads();
        if (more) cur ^= 1;
    }

    ull* redU = (ull*)&As[0][0][0];
    if (kg == 1) {
        #pragma unroll
        for (int i = 0; i < 8; ++i) {
            redU[lt * 16 + i * 2 + 0] = acc[i][0];
            redU[lt * 16 + i * 2 + 1] = acc[i][1];
        }
    }
    __syncthreads();
    if (kg != 0) return;

    float alpha = 1.f;
    if (SCALE) alpha = *alpha_ptr;
    float4 bv;
    if (BIAS) bv = *(const float4*)&bias[col0 + tx * 4];

    #pragma unroll
    for (int i = 0; i < 8; ++i) {
        int r = row0 + ty * 8 + i;
        int c = col0 + tx * 4;
        float2 o0 = up2(acc[i][0]);
        float2 o1 = up2(acc[i][1]);
        float2 p0 = up2(redU[lt * 16 + i * 2 + 0]);
        float2 p1 = up2(redU[lt * 16 + i * 2 + 1]);
        float4 v = make_float4(o0.x + p0.x, o0.y + p0.y, o1.x + p1.x, o1.y + p1.y);
        if (BIAS) { v.x += bv.x; v.y += bv.y; v.z += bv.z; v.w += bv.w; }
        if (RELU) {
            v.x = fmaxf(v.x, 0.f); v.y = fmaxf(v.y, 0.f);
            v.z = fmaxf(v.z, 0.f); v.w = fmaxf(v.w, 0.f);
        }
        v.x *= alpha; v.y *= alpha; v.z *= alpha; v.w *= alpha;
        *(float4*)&C[(long)r * ldc + c] = v;
    }
}

// ---------------- pairwise v3: 2 p-rows per block, 256 threads, dynamic smem ----------------
// Halves (tid<128 / tid>=128) each run the proven 128-thread path for one p.
// Shared across halves: Wc_s (Ws1 rows 48..95), ws2, Zis q-tile. Per-half: Gs, logits, tjb, Zjp.
#define PW_WC_OFF     0
#define PW_ZIS_OFF    (48*96)                    // 4608 floats
#define PW_GS_OFF     (PW_ZIS_OFF + 128*25)      // 3200 floats
#define PW_LOG_OFF    (PW_GS_OFF + 2*24*128)     // 6144 floats
#define PW_TJB_OFF    (PW_LOG_OFF + 2*512)
#define PW_WS2_OFF    (PW_TJB_OFF + 2*96)
#define PW_ZJP_OFF    (PW_WS2_OFF + 96)
#define PW_RED_OFF    (PW_ZJP_OFF + 2*24)
#define PW_SMEM_FLOATS (PW_RED_OFF + 2*8)
#define PW_SMEM_BYTES  (PW_SMEM_FLOATS*4)        // ~61.7 KB

__global__ __launch_bounds__(256)
void pairwise_kernel(const float* __restrict__ Zj, const float* __restrict__ Zi,
                     const float* __restrict__ tjb, const float* __restrict__ ti,
                     const float* __restrict__ Ws1, const float* __restrict__ ws2,
                     const float* __restrict__ bs2, const int* __restrict__ attn_mask,
                     float* __restrict__ probs)
{
    extern __shared__ float dyn[];
    float* Wc_s   = dyn + PW_WC_OFF;     // [48][96]
    float* ZisT   = dyn + PW_ZIS_OFF;    // [128][25]

    const int tid = threadIdx.x;
    const int half = tid >> 7;
    const int t = tid & 127;
    const int tx = t & 7;
    const int ty = t >> 3;
    const int pg = blockIdx.x * 2 + half;
    const int b = pg >> 9;

    float* GsH    = dyn + PW_GS_OFF  + half * (24 * 128);  // [24][128]
    float* logH   = dyn + PW_LOG_OFF + half * 512;
    float* tjbH   = dyn + PW_TJB_OFF + half * 96;
    float* ws2_s  = dyn + PW_WS2_OFF;
    float* ZjpH   = dyn + PW_ZJP_OFF + half * 24;
    float* redH   = dyn + PW_RED_OFF + half * 8;

    // shared loads (256 threads)
    for (int idx = tid; idx < 48 * 96; idx += 256)
        Wc_s[idx] = Ws1[48 * 96 + idx];
    if (tid < 96) ws2_s[tid] = ws2[tid];
    // per-half loads (128 threads each)
    if (t < 24) ZjpH[t] = Zj[pg * 24 + t];
    if (t < 96) tjbH[t] = tjb[pg * 96 + t];
    __syncthreads();

    #pragma unroll 1
    for (int qt = 0; qt < 4; ++qt) {
        const int q0 = qt * 128;
        // load Zi tile (shared; 256 threads)
        for (int idx = tid; idx < 128 * 24; idx += 256) {
            int q = idx / 24, d = idx - q * 24;
            ZisT[q * 25 + d] = Zi[((long)(b * 512 + q0 + q)) * 24 + d];
        }
        __syncthreads();

        ull acc[8][6];
        #pragma unroll
        for (int i = 0; i < 8; ++i)
            #pragma unroll
            for (int j = 0; j < 6; ++j) acc[i][j] = 0ull;

        #pragma unroll 1
        for (int ph = 0; ph < 2; ++ph) {
            // build G phase for this half's p
            for (int idx = t; idx < 24 * 128; idx += 128) {
                int k = idx >> 7, q = idx & 127;
                float zj = ZjpH[k], zi = ZisT[q * 25 + k];
                GsH[k * 128 + q] = ph ? fabsf(zj - zi) : zj * zi;
            }
            __syncthreads();
            const int kbase = ph * 24;
            #pragma unroll
            for (int k = 0; k < 24; ++k) {
                float4 g0 = *(const float4*)&GsH[k * 128 + ty * 8];
                float4 g1 = *(const float4*)&GsH[k * 128 + ty * 8 + 4];
                const float* wrow = &Wc_s[(kbase + k) * 96 + tx * 12];
                ulonglong2 w0 = *(const ulonglong2*)&wrow[0];
                ulonglong2 w1 = *(const ulonglong2*)&wrow[4];
                ulonglong2 w2 = *(const ulonglong2*)&wrow[8];
                ull gp[8];
                gp[0] = pk2(g0.x); gp[1] = pk2(g0.y); gp[2] = pk2(g0.z); gp[3] = pk2(g0.w);
                gp[4] = pk2(g1.x); gp[5] = pk2(g1.y); gp[6] = pk2(g1.z); gp[7] = pk2(g1.w);
                #pragma unroll
                for (int i = 0; i < 8; ++i) {
                    fma2(acc[i][0], gp[i], w0.x);
                    fma2(acc[i][1], gp[i], w0.y);
                    fma2(acc[i][2], gp[i], w1.x);
                    fma2(acc[i][3], gp[i], w1.y);
                    fma2(acc[i][4], gp[i], w2.x);
                    fma2(acc[i][5], gp[i], w2.y);
                }
            }
            __syncthreads();
        }

        // epilogue: + tjb + ti, relu, dot ws2, reduce over 8 tx lanes
        #pragma unroll
        for (int i = 0; i < 8; ++i) {
            int q = ty * 8 + i;
            const float* tirow = &ti[((long)(b * 512 + q0 + q)) * 96 + tx * 12];
            float s = 0.f;
            #pragma unroll
            for (int j = 0; j < 6; ++j) {
                int m = tx * 12 + 2 * j;
                float2 a = up2(acc[i][j]);
                float2 tv = *(const float2*)&tirow[2 * j];
                float h0 = fmaxf(a.x + tjbH[m] + tv.x, 0.f);
                float h1 = fmaxf(a.y + tjbH[m + 1] + tv.y, 0.f);
                s = fmaf(h0, ws2_s[m], s);
                s = fmaf(h1, ws2_s[m + 1], s);
            }
            s += __shfl_xor_sync(0xffffffffu, s, 1);
            s += __shfl_xor_sync(0xffffffffu, s, 2);
            s += __shfl_xor_sync(0xffffffffu, s, 4);
            if (tx == 0) logH[q0 + q] = s;
        }
    }
    __syncthreads();

    // mask + bs2 (per half)
    const float bs2v = *bs2;
    #pragma unroll
    for (int q = t; q < 512; q += 128) {
        float mv = (float)attn_mask[b * 512 + q];
        logH[q] += bs2v + (1.f - mv) * (-3.402823466e38f);
    }
    __syncthreads();

    // softmax over 512 within the half (warps 0-3 / 4-7)
    const int wid2 = t >> 5, lane = t & 31;
    float lmax = -INFINITY;
    #pragma unroll
    for (int q = t; q < 512; q += 128) lmax = fmaxf(lmax, logH[q]);
    #pragma unroll
    for (int o = 16; o > 0; o >>= 1) lmax = fmaxf(lmax, __shfl_xor_sync(0xffffffffu, lmax, o));
    if (lane == 0) redH[wid2] = lmax;
    __syncthreads();
    lmax = fmaxf(fmaxf(redH[0], redH[1]), fmaxf(redH[2], redH[3]));

    float lsum = 0.f;
    float ev[4];
    #pragma unroll
    for (int u = 0; u < 4; ++u) {
        int q = t + u * 128;
        ev[u] = expf(logH[q] - lmax);
        lsum += ev[u];
    }
    #pragma unroll
    for (int o = 16; o > 0; o >>= 1) lsum += __shfl_xor_sync(0xffffffffu, lsum, o);
    if (lane == 0) redH[4 + wid2] = lsum;
    __syncthreads();
    const float inv = 1.f / (redH[4] + redH[5] + redH[6] + redH[7]);
    #pragma unroll
    for (int u = 0; u < 4; ++u) {
        int q = t + u * 128;
        probs[(long)pg * 512 + q] = ev[u] * inv;
    }
}

// ---------------- launch ----------------
extern "C" void kernel_launch(void* const* d_in, const int* in_sizes, int n_in,
                              void* d_out, int out_size)
{
    const float* Hj   = (const float*)d_in[0];
    const float* Hi   = (const float*)d_in[1];
    const float* Wpj  = (const float*)d_in[2];
    const float* Wpi  = (const float*)d_in[3];
    const float* Ws1  = (const float*)d_in[4];
    const float* bs1  = (const float*)d_in[5];
    const float* ws2  = (const float*)d_in[6];
    const float* bs2  = (const float*)d_in[7];
    const float* Wv1  = (const float*)d_in[8];
    const float* bv1  = (const float*)d_in[9];
    const float* Wv2  = (const float*)d_in[10];
    const float* bv2  = (const float*)d_in[11];
    const float* alpha= (const float*)d_in[12];
    const int*   mask = (const int*)d_in[13];
    float* out = (float*)d_out;

    float *Zj, *Zi, *tjb, *ti, *probs, *ctx, *mhid;
    cudaGetSymbolAddress((void**)&Zj, g_Zj);
    cudaGetSymbolAddress((void**)&Zi, g_Zi);
    cudaGetSymbolAddress((void**)&tjb, g_tjb);
    cudaGetSymbolAddress((void**)&ti, g_ti);
    cudaGetSymbolAddress((void**)&probs, g_probs);
    cudaGetSymbolAddress((void**)&ctx, g_ctx);
    cudaGetSymbolAddress((void**)&mhid, g_mhid);

    static int attr_done = 0;
    if (!attr_done) {
        cudaFuncSetAttribute(pairwise_kernel,
                             cudaFuncAttributeMaxDynamicSharedMemorySize, PW_SMEM_BYTES);
        attr_done = 1;
    }

    // Zj = H_j @ Wpj ; Zi = H_i @ Wpi   (2048 x 24, K=768), batched
    sgemm_small2<<<dim3(1, ROWS/64, 2), 256>>>(
        Hj, Wpj, Zj, nullptr, Hi, Wpi, Zi, nullptr,
        ROWS, DD, HD, HD, DD, DD);

    // tjb = Zj @ Ws1[0:24] + bs1 ; ti = Zi @ Ws1[24:48]   (2048 x 96, K=24), batched
    sgemm_small2<<<dim3(2, ROWS/64, 2), 256>>>(
        Zj, Ws1, tjb, bs1, Zi, Ws1 + DD * MMDIM, ti, nullptr,
        ROWS, MMDIM, DD, DD, MMDIM, MMDIM);

    // fused pairwise logits + softmax -> probs (2 p per block)
    pairwise_kernel<<<ROWS/2, 256, PW_SMEM_BYTES>>>(
        Zj, Zi, tjb, ti, Ws1, ws2, bs2, mask, probs);

    // ctx = probs @ H_i   (batched 4x: 512 x 768, K=512)
    gemmks<0,false,false,false><<<dim3(HD/64, SEQ/64, BATCH), 256>>>(
        probs, Hi, ctx, SEQ, SEQ, HD, HD, nullptr, nullptr,
        (long)SEQ*SEQ, (long)SEQ*HD, (long)SEQ*HD, nullptr, nullptr);

    // mhid = relu([ctx|Hj|ctx*Hj] @ Wv1 + bv1)   (2048 x 768, K=2304; X fused)
    gemmks<1,true,true,false><<<dim3(OO/64, ROWS/64, 1), 256>>>(
        nullptr, Wv1, mhid, XCOLS, 0, OO, OO, bv1, nullptr,
        0, 0, 0, ctx, Hj);

    // out = alpha * (mhid @ Wv2 + bv2)   (2048 x 768, K=768)
    gemmks<0,true,false,true><<<dim3(HD/64, ROWS/64, 1), 256>>>(
        mhid, Wv2, out, OO, OO, HD, HD, bv2, alpha,
        0, 0, 0, nullptr, nullptr);
}

// round 9
// speedup vs baseline: 1.9229x; 1.2486x over previous
#include <cuda_runtime.h>
#include <math.h>

#define BATCH 4
#define SEQ   512
#define HD    768
#define DD    24
#define MMDIM 96
#define OO    768
#define ROWS  (BATCH*SEQ)       // 2048
#define XCOLS (3*HD)            // 2304

typedef unsigned long long ull;

// ---------------- scratch (no allocations allowed) ----------------
__device__ float g_Zj[ROWS*DD];
__device__ float g_Zi[ROWS*DD];
__device__ float g_tjb[ROWS*MMDIM];
__device__ float g_probs[(long)BATCH*SEQ*SEQ];
__device__ float g_ctx[(long)ROWS*HD];
__device__ float g_mhid[(long)ROWS*OO];

// ---------------- packed f32x2 helpers ----------------
__device__ __forceinline__ ull pk2(float x) {
    ull r; asm("mov.b64 %0, {%1, %1};" : "=l"(r) : "f"(x)); return r;
}
__device__ __forceinline__ void fma2(ull &d, ull a, ull b) {
    asm("fma.rn.f32x2 %0, %1, %2, %0;" : "+l"(d) : "l"(a), "l"(b));
}
__device__ __forceinline__ float2 up2(ull v) {
    float2 r; asm("mov.b64 {%0, %1}, %2;" : "=f"(r.x), "=f"(r.y) : "l"(v)); return r;
}

// ---------------- small generic SGEMM, z-batched over pointer pairs ----------------
__global__ __launch_bounds__(256)
void sgemm_small2(const float* __restrict__ A0, const float* __restrict__ B0,
                  float* __restrict__ C0, const float* __restrict__ bias0,
                  const float* __restrict__ A1, const float* __restrict__ B1,
                  float* __restrict__ C1, const float* __restrict__ bias1,
                  int M, int N, int K, int lda, int ldb, int ldc)
{
    __shared__ float As[16][64];
    __shared__ float Bs[16][64];
    const float* A = blockIdx.z ? A1 : A0;
    const float* B = blockIdx.z ? B1 : B0;
    float*       C = blockIdx.z ? C1 : C0;
    const float* bias = blockIdx.z ? bias1 : bias0;

    const int tid = threadIdx.x;
    const int tx = tid & 15, ty = tid >> 4;
    const int row0 = blockIdx.y * 64;
    const int col0 = blockIdx.x * 64;

    float acc[4][4] = {};
    for (int k0 = 0; k0 < K; k0 += 16) {
        #pragma unroll
        for (int u = 0; u < 4; ++u) {
            int t = tid + u * 256;
            int r = t >> 4, kk = t & 15;
            int gr = row0 + r, gk = k0 + kk;
            float v = 0.f;
            if (gr < M && gk < K) v = A[(long)gr * lda + gk];
            As[kk][r] = v;
        }
        #pragma unroll
        for (int u = 0; u < 4; ++u) {
            int t = tid + u * 256;
            int kk = t >> 6, n = t & 63;
            int gk = k0 + kk, gn = col0 + n;
            float v = 0.f;
            if (gk < K && gn < N) v = B[(long)gk * ldb + gn];
            Bs[kk][n] = v;
        }
        __syncthreads();
        #pragma unroll
        for (int kk = 0; kk < 16; ++kk) {
            float4 a4 = *(const float4*)&As[kk][ty * 4];
            float4 b4 = *(const float4*)&Bs[kk][tx * 4];
            float a[4] = {a4.x, a4.y, a4.z, a4.w};
            float b[4] = {b4.x, b4.y, b4.z, b4.w};
            #pragma unroll
            for (int i = 0; i < 4; ++i)
                #pragma unroll
                for (int j = 0; j < 4; ++j)
                    acc[i][j] = fmaf(a[i], b[j], acc[i][j]);
        }
        __syncthreads();
    }
    #pragma unroll
    for (int i = 0; i < 4; ++i) {
        int r = row0 + ty * 4 + i;
        if (r >= M) continue;
        #pragma unroll
        for (int j = 0; j < 4; ++j) {
            int c = col0 + tx * 4 + j;
            if (c >= N) continue;
            float v = acc[i][j];
            if (bias) v += bias[c];
            C[(long)r * ldc + c] = v;
        }
    }
}

// ---------------- gemmks: 64x64 tile, 256 threads, intra-block split-K x2 (R6, frozen) ----------------
template<int AMODE, bool BIAS, bool RELU, bool SCALE>
__global__ __launch_bounds__(256)
void gemmks(const float* __restrict__ A, const float* __restrict__ B,
            float* __restrict__ C, int K, int lda, int ldb, int ldc,
            const float* __restrict__ bias, const float* __restrict__ alpha_ptr,
            long sA, long sB, long sC,
            const float* __restrict__ Actx, const float* __restrict__ Ahj)
{
    __shared__ float As[2][32][68];
    __shared__ float Bs[2][32][68];

    const int bz = blockIdx.z;
    if (AMODE == 0) A += (long)bz * sA;
    B += (long)bz * sB;  C += (long)bz * sC;

    const int tid = threadIdx.x;
    const int kg = tid >> 7;
    const int lt = tid & 127;
    const int tx = lt & 15;
    const int ty = lt >> 4;
    const int row0 = blockIdx.y * 64;
    const int col0 = blockIdx.x * 64;

    ull acc[8][2];
    #pragma unroll
    for (int i = 0; i < 8; ++i) { acc[i][0] = 0ull; acc[i][1] = 0ull; }

    float4 pa[2], pb[2];

    auto loadA = [&](int kt) {
        #pragma unroll
        for (int u = 0; u < 2; ++u) {
            int lin = tid + u * 256;
            int r = lin >> 3, kc = lin & 7;
            int gk = kt + kc * 4;
            if (AMODE == 0) {
                pa[u] = *(const float4*)&A[(long)(row0 + r) * lda + gk];
            } else {
                long ridx = (long)(row0 + r) * HD;
                if (gk < HD) {
                    pa[u] = *(const float4*)&Actx[ridx + gk];
                } else if (gk < 2 * HD) {
                    pa[u] = *(const float4*)&Ahj[ridx + gk - HD];
                } else {
                    float4 c4 = *(const float4*)&Actx[ridx + gk - 2 * HD];
                    float4 h4 = *(const float4*)&Ahj[ridx + gk - 2 * HD];
                    pa[u].x = c4.x * h4.x; pa[u].y = c4.y * h4.y;
                    pa[u].z = c4.z * h4.z; pa[u].w = c4.w * h4.w;
                }
            }
        }
    };
    auto loadB = [&](int kt) {
        #pragma unroll
        for (int u = 0; u < 2; ++u) {
            int lin = tid + u * 256;
            int bkr = lin >> 4, bn4 = lin & 15;
            pb[u] = *(const float4*)&B[(long)(kt + bkr) * ldb + col0 + bn4 * 4];
        }
    };
    auto storeTiles = [&](int buf) {
        #pragma unroll
        for (int u = 0; u < 2; ++u) {
            int lin = tid + u * 256;
            int r = lin >> 3, kc = lin & 7;
            As[buf][kc * 4 + 0][r] = pa[u].x;
            As[buf][kc * 4 + 1][r] = pa[u].y;
            As[buf][kc * 4 + 2][r] = pa[u].z;
            As[buf][kc * 4 + 3][r] = pa[u].w;
            int bkr = lin >> 4, bn4 = lin & 15;
            *(float4*)&Bs[buf][bkr][bn4 * 4] = pb[u];
        }
    };

    loadA(0); loadB(0);
    storeTiles(0);
    __syncthreads();

    int cur = 0;
    for (int kt = 0; kt < K; kt += 32) {
        const bool more = (kt + 32) < K;
        if (more) { loadA(kt + 32); loadB(kt + 32); }

        #pragma unroll
        for (int kk = 0; kk < 16; ++kk) {
            const int k = kg * 16 + kk;
            float4 a0 = *(const float4*)&As[cur][k][ty * 8];
            float4 a1 = *(const float4*)&As[cur][k][ty * 8 + 4];
            ulonglong2 bl = *(const ulonglong2*)&Bs[cur][k][tx * 4];
            ull ap[8];
            ap[0] = pk2(a0.x); ap[1] = pk2(a0.y); ap[2] = pk2(a0.z); ap[3] = pk2(a0.w);
            ap[4] = pk2(a1.x); ap[5] = pk2(a1.y); ap[6] = pk2(a1.z); ap[7] = pk2(a1.w);
            #pragma unroll
            for (int i = 0; i < 8; ++i) {
                fma2(acc[i][0], ap[i], bl.x);
                fma2(acc[i][1], ap[i], bl.y);
            }
        }
        if (more) {
            storeTiles(cur ^ 1);
        }
        __syncthreads();
        if (more) cur ^= 1;
    }

    ull* redU = (ull*)&As[0][0][0];
    if (kg == 1) {
        #pragma unroll
        for (int i = 0; i < 8; ++i) {
            redU[lt * 16 + i * 2 + 0] = acc[i][0];
            redU[lt * 16 + i * 2 + 1] = acc[i][1];
        }
    }
    __syncthreads();
    if (kg != 0) return;

    float alpha = 1.f;
    if (SCALE) alpha = *alpha_ptr;
    float4 bv;
    if (BIAS) bv = *(const float4*)&bias[col0 + tx * 4];

    #pragma unroll
    for (int i = 0; i < 8; ++i) {
        int r = row0 + ty * 8 + i;
        int c = col0 + tx * 4;
        float2 o0 = up2(acc[i][0]);
        float2 o1 = up2(acc[i][1]);
        float2 p0 = up2(redU[lt * 16 + i * 2 + 0]);
        float2 p1 = up2(redU[lt * 16 + i * 2 + 1]);
        float4 v = make_float4(o0.x + p0.x, o0.y + p0.y, o1.x + p1.x, o1.y + p1.y);
        if (BIAS) { v.x += bv.x; v.y += bv.y; v.z += bv.z; v.w += bv.w; }
        if (RELU) {
            v.x = fmaxf(v.x, 0.f); v.y = fmaxf(v.y, 0.f);
            v.z = fmaxf(v.z, 0.f); v.w = fmaxf(v.w, 0.f);
        }
        v.x *= alpha; v.y *= alpha; v.z *= alpha; v.w *= alpha;
        *(float4*)&C[(long)r * ldc + c] = v;
    }
}

// ---------------- pairwise v4: per-block folded weights, no ti, no product build ----------------
// Identity: th+ti = Zi @ (W1i + zjp*W1h)  =>  logits_pre = [Zi | |zjp-Zi|] @ [W'; W1d] + tjb
// Per block (one p, 128 threads): Wc_s rows 0..23 = W' (computed once), rows 24..47 = W1d.
// Per q-tile of 128: Gs rows 0..23 = Zi (k-major), rows 24..47 = |diff|; single 48-k FFMA2 loop.
__global__ __launch_bounds__(128)
void pairwise_kernel(const float* __restrict__ Zj, const float* __restrict__ Zi,
                     const float* __restrict__ tjb,
                     const float* __restrict__ Ws1, const float* __restrict__ ws2,
                     const float* __restrict__ bs2, const int* __restrict__ attn_mask,
                     float* __restrict__ probs)
{
    __shared__ float Wc_s[48][96];     // 18 KB
    __shared__ float Gs[48][128];      // 24 KB
    __shared__ float logits_s[512];
    __shared__ float Zjp_s[24];
    __shared__ float tjb_s[96];
    __shared__ float ws2_s[96];
    __shared__ float red_s[8];

    const int tid = threadIdx.x;
    const int tx = tid & 7;
    const int ty = tid >> 3;
    const int pg = blockIdx.x;
    const int b = pg >> 9;

    if (tid < 24) Zjp_s[tid] = Zj[pg * 24 + tid];
    if (tid < 96) { tjb_s[tid] = tjb[pg * 96 + tid]; ws2_s[tid] = ws2[tid]; }
    __syncthreads();

    // Per-block weights: W'[d] = W1i[d] + zjp[d]*W1h[d]  (Ws1 rows 24..47 / 48..71),
    // and W1d (rows 72..95) into the lower half.
    for (int idx = tid; idx < 24 * 96; idx += 128) {
        int d = idx / 96, m = idx - d * 96;
        Wc_s[d][m]      = fmaf(Zjp_s[d], Ws1[(48 + d) * 96 + m], Ws1[(24 + d) * 96 + m]);
        Wc_s[24 + d][m] = Ws1[(72 + d) * 96 + m];
    }
    __syncthreads();

    #pragma unroll 1
    for (int qt = 0; qt < 4; ++qt) {
        const int q0 = qt * 128;
        // build G: each thread owns one q (its Zi row, 96 B = 6 float4)
        {
            const int q = tid;
            const float* zrow = &Zi[((long)(b * 512 + q0 + q)) * 24];
            float4 z4[6];
            #pragma unroll
            for (int u = 0; u < 6; ++u) z4[u] = *(const float4*)&zrow[u * 4];
            const float zv[24] = {z4[0].x, z4[0].y, z4[0].z, z4[0].w,
                                  z4[1].x, z4[1].y, z4[1].z, z4[1].w,
                                  z4[2].x, z4[2].y, z4[2].z, z4[2].w,
                                  z4[3].x, z4[3].y, z4[3].z, z4[3].w,
                                  z4[4].x, z4[4].y, z4[4].z, z4[4].w,
                                  z4[5].x, z4[5].y, z4[5].z, z4[5].w};
            #pragma unroll
            for (int d = 0; d < 24; ++d) {
                Gs[d][q]      = zv[d];
                Gs[24 + d][q] = fabsf(Zjp_s[d] - zv[d]);
            }
        }
        __syncthreads();

        ull acc[8][6];
        #pragma unroll
        for (int i = 0; i < 8; ++i)
            #pragma unroll
            for (int j = 0; j < 6; ++j) acc[i][j] = 0ull;

        #pragma unroll
        for (int k = 0; k < 48; ++k) {
            float4 g0 = *(const float4*)&Gs[k][ty * 8];
            float4 g1 = *(const float4*)&Gs[k][ty * 8 + 4];
            ulonglong2 w0 = *(const ulonglong2*)&Wc_s[k][tx * 12];
            ulonglong2 w1 = *(const ulonglong2*)&Wc_s[k][tx * 12 + 4];
            ulonglong2 w2 = *(const ulonglong2*)&Wc_s[k][tx * 12 + 8];
            ull gp[8];
            gp[0] = pk2(g0.x); gp[1] = pk2(g0.y); gp[2] = pk2(g0.z); gp[3] = pk2(g0.w);
            gp[4] = pk2(g1.x); gp[5] = pk2(g1.y); gp[6] = pk2(g1.z); gp[7] = pk2(g1.w);
            #pragma unroll
            for (int i = 0; i < 8; ++i) {
                fma2(acc[i][0], gp[i], w0.x);
                fma2(acc[i][1], gp[i], w0.y);
                fma2(acc[i][2], gp[i], w1.x);
                fma2(acc[i][3], gp[i], w1.y);
                fma2(acc[i][4], gp[i], w2.x);
                fma2(acc[i][5], gp[i], w2.y);
            }
        }

        // epilogue: + tjb (has bias), relu, dot ws2, reduce over the 8 tx lanes
        #pragma unroll
        for (int i = 0; i < 8; ++i) {
            int q = ty * 8 + i;
            float s = 0.f;
            #pragma unroll
            for (int j = 0; j < 6; ++j) {
                int m = tx * 12 + 2 * j;
                float2 a = up2(acc[i][j]);
                float h0 = fmaxf(a.x + tjb_s[m], 0.f);
                float h1 = fmaxf(a.y + tjb_s[m + 1], 0.f);
                s = fmaf(h0, ws2_s[m], s);
                s = fmaf(h1, ws2_s[m + 1], s);
            }
            s += __shfl_xor_sync(0xffffffffu, s, 1);
            s += __shfl_xor_sync(0xffffffffu, s, 2);
            s += __shfl_xor_sync(0xffffffffu, s, 4);
            if (tx == 0) logits_s[q0 + q] = s;
        }
        __syncthreads();
    }

    // mask + bs2
    const float bs2v = *bs2;
    #pragma unroll
    for (int q = tid; q < 512; q += 128) {
        float mv = (float)attn_mask[b * 512 + q];
        logits_s[q] += bs2v + (1.f - mv) * (-3.402823466e38f);
    }
    __syncthreads();

    const int wid = tid >> 5, lane = tid & 31;
    float lmax = -INFINITY;
    #pragma unroll
    for (int q = tid; q < 512; q += 128) lmax = fmaxf(lmax, logits_s[q]);
    #pragma unroll
    for (int o = 16; o > 0; o >>= 1) lmax = fmaxf(lmax, __shfl_xor_sync(0xffffffffu, lmax, o));
    if (lane == 0) red_s[wid] = lmax;
    __syncthreads();
    lmax = fmaxf(fmaxf(red_s[0], red_s[1]), fmaxf(red_s[2], red_s[3]));

    float lsum = 0.f;
    float ev[4];
    #pragma unroll
    for (int u = 0; u < 4; ++u) {
        int q = tid + u * 128;
        ev[u] = expf(logits_s[q] - lmax);
        lsum += ev[u];
    }
    #pragma unroll
    for (int o = 16; o > 0; o >>= 1) lsum += __shfl_xor_sync(0xffffffffu, lsum, o);
    if (lane == 0) red_s[4 + wid] = lsum;
    __syncthreads();
    const float inv = 1.f / (red_s[4] + red_s[5] + red_s[6] + red_s[7]);
    #pragma unroll
    for (int u = 0; u < 4; ++u) {
        int q = tid + u * 128;
        probs[(long)pg * 512 + q] = ev[u] * inv;
    }
}

// ---------------- launch ----------------
extern "C" void kernel_launch(void* const* d_in, const int* in_sizes, int n_in,
                              void* d_out, int out_size)
{
    const float* Hj   = (const float*)d_in[0];
    const float* Hi   = (const float*)d_in[1];
    const float* Wpj  = (const float*)d_in[2];
    const float* Wpi  = (const float*)d_in[3];
    const float* Ws1  = (const float*)d_in[4];
    const float* bs1  = (const float*)d_in[5];
    const float* ws2  = (const float*)d_in[6];
    const float* bs2  = (const float*)d_in[7];
    const float* Wv1  = (const float*)d_in[8];
    const float* bv1  = (const float*)d_in[9];
    const float* Wv2  = (const float*)d_in[10];
    const float* bv2  = (const float*)d_in[11];
    const float* alpha= (const float*)d_in[12];
    const int*   mask = (const int*)d_in[13];
    float* out = (float*)d_out;

    float *Zj, *Zi, *tjb, *probs, *ctx, *mhid;
    cudaGetSymbolAddress((void**)&Zj, g_Zj);
    cudaGetSymbolAddress((void**)&Zi, g_Zi);
    cudaGetSymbolAddress((void**)&tjb, g_tjb);
    cudaGetSymbolAddress((void**)&probs, g_probs);
    cudaGetSymbolAddress((void**)&ctx, g_ctx);
    cudaGetSymbolAddress((void**)&mhid, g_mhid);

    // Zj = H_j @ Wpj ; Zi = H_i @ Wpi   (2048 x 24, K=768), batched
    sgemm_small2<<<dim3(1, ROWS/64, 2), 256>>>(
        Hj, Wpj, Zj, nullptr, Hi, Wpi, Zi, nullptr,
        ROWS, DD, HD, HD, DD, DD);

    // tjb = Zj @ Ws1[0:24] + bs1   (2048 x 96, K=24)  — ti no longer needed
    sgemm_small2<<<dim3(2, ROWS/64, 1), 256>>>(
        Zj, Ws1, tjb, bs1, nullptr, nullptr, nullptr, nullptr,
        ROWS, MMDIM, DD, DD, MMDIM, MMDIM);

    // fused pairwise logits + softmax -> probs
    pairwise_kernel<<<ROWS, 128>>>(Zj, Zi, tjb, Ws1, ws2, bs2, mask, probs);

    // ctx = probs @ H_i   (batched 4x: 512 x 768, K=512)
    gemmks<0,false,false,false><<<dim3(HD/64, SEQ/64, BATCH), 256>>>(
        probs, Hi, ctx, SEQ, SEQ, HD, HD, nullptr, nullptr,
        (long)SEQ*SEQ, (long)SEQ*HD, (long)SEQ*HD, nullptr, nullptr);

    // mhid = relu([ctx|Hj|ctx*Hj] @ Wv1 + bv1)   (2048 x 768, K=2304; X fused)
    gemmks<1,true,true,false><<<dim3(OO/64, ROWS/64, 1), 256>>>(
        nullptr, Wv1, mhid, XCOLS, 0, OO, OO, bv1, nullptr,
        0, 0, 0, ctx, Hj);

    // out = alpha * (mhid @ Wv2 + bv2)   (2048 x 768, K=768)
    gemmks<0,true,false,true><<<dim3(HD/64, ROWS/64, 1), 256>>>(
        mhid, Wv2, out, OO, OO, HD, HD, bv2, alpha,
        0, 0, 0, nullptr, nullptr);
}

// round 10
// speedup vs baseline: 2.3072x; 1.1999x over previous
#include <cuda_runtime.h>
#include <math.h>

#define BATCH 4
#define SEQ   512
#define HD    768
#define DD    24
#define MMDIM 96
#define OO    768
#define ROWS  (BATCH*SEQ)       // 2048
#define XCOLS (3*HD)            // 2304

typedef unsigned long long ull;
typedef unsigned int uint;

// ---------------- scratch (no allocations allowed) ----------------
__device__ float g_Zj[ROWS*DD];
__device__ float g_Zi[ROWS*DD];
__device__ float g_tjb[ROWS*MMDIM];
__device__ float g_probs[(long)BATCH*SEQ*SEQ];
__device__ float g_ctx[(long)ROWS*HD];
__device__ float g_mhid[(long)ROWS*OO];

// ---------------- packed f32x2 helpers ----------------
__device__ __forceinline__ ull pk2(float x) {
    ull r; asm("mov.b64 %0, {%1, %1};" : "=l"(r) : "f"(x)); return r;
}
__device__ __forceinline__ void fma2(ull &d, ull a, ull b) {
    asm("fma.rn.f32x2 %0, %1, %2, %0;" : "+l"(d) : "l"(a), "l"(b));
}
__device__ __forceinline__ float2 up2(ull v) {
    float2 r; asm("mov.b64 {%0, %1}, %2;" : "=f"(r.x), "=f"(r.y) : "l"(v)); return r;
}

// ---------------- tf32 helpers ----------------
__device__ __forceinline__ uint f2tf(float x) {
    uint r; asm("cvt.rna.tf32.f32 %0, %1;" : "=r"(r) : "f"(x)); return r;
}
__device__ __forceinline__ void mma_tf32(float* c, const uint* a, const uint* b) {
    asm volatile(
        "mma.sync.aligned.m16n8k8.row.col.f32.tf32.tf32.f32 "
        "{%0,%1,%2,%3}, {%4,%5,%6,%7}, {%8,%9}, {%0,%1,%2,%3};"
        : "+f"(c[0]), "+f"(c[1]), "+f"(c[2]), "+f"(c[3])
        : "r"(a[0]), "r"(a[1]), "r"(a[2]), "r"(a[3]), "r"(b[0]), "r"(b[1]));
}

// ---------------- small generic SGEMM, z-batched over pointer pairs ----------------
__global__ __launch_bounds__(256)
void sgemm_small2(const float* __restrict__ A0, const float* __restrict__ B0,
                  float* __restrict__ C0, const float* __restrict__ bias0,
                  const float* __restrict__ A1, const float* __restrict__ B1,
                  float* __restrict__ C1, const float* __restrict__ bias1,
                  int M, int N, int K, int lda, int ldb, int ldc)
{
    __shared__ float As[16][64];
    __shared__ float Bs[16][64];
    const float* A = blockIdx.z ? A1 : A0;
    const float* B = blockIdx.z ? B1 : B0;
    float*       C = blockIdx.z ? C1 : C0;
    const float* bias = blockIdx.z ? bias1 : bias0;

    const int tid = threadIdx.x;
    const int tx = tid & 15, ty = tid >> 4;
    const int row0 = blockIdx.y * 64;
    const int col0 = blockIdx.x * 64;

    float acc[4][4] = {};
    for (int k0 = 0; k0 < K; k0 += 16) {
        #pragma unroll
        for (int u = 0; u < 4; ++u) {
            int t = tid + u * 256;
            int r = t >> 4, kk = t & 15;
            int gr = row0 + r, gk = k0 + kk;
            float v = 0.f;
            if (gr < M && gk < K) v = A[(long)gr * lda + gk];
            As[kk][r] = v;
        }
        #pragma unroll
        for (int u = 0; u < 4; ++u) {
            int t = tid + u * 256;
            int kk = t >> 6, n = t & 63;
            int gk = k0 + kk, gn = col0 + n;
            float v = 0.f;
            if (gk < K && gn < N) v = B[(long)gk * ldb + gn];
            Bs[kk][n] = v;
        }
        __syncthreads();
        #pragma unroll
        for (int kk = 0; kk < 16; ++kk) {
            float4 a4 = *(const float4*)&As[kk][ty * 4];
            float4 b4 = *(const float4*)&Bs[kk][tx * 4];
            float a[4] = {a4.x, a4.y, a4.z, a4.w};
            float b[4] = {b4.x, b4.y, b4.z, b4.w};
            #pragma unroll
            for (int i = 0; i < 4; ++i)
                #pragma unroll
                for (int j = 0; j < 4; ++j)
                    acc[i][j] = fmaf(a[i], b[j], acc[i][j]);
        }
        __syncthreads();
    }
    #pragma unroll
    for (int i = 0; i < 4; ++i) {
        int r = row0 + ty * 4 + i;
        if (r >= M) continue;
        #pragma unroll
        for (int j = 0; j < 4; ++j) {
            int c = col0 + tx * 4 + j;
            if (c >= N) continue;
            float v = acc[i][j];
            if (bias) v += bias[c];
            C[(long)r * ldc + c] = v;
        }
    }
}

// ---------------- gemm_tc: 64x64 tile, 128 threads, tf32 mma.sync ----------------
// 4 warps; warp tile 32x32 = 2 m-frags x 4 n-frags of m16n8k8. ktile=16, double-buffered.
// cvt.rna to tf32 once at smem-store time. Smem strides 20/72 make all fragment
// LDS.32 patterns conflict-free. Exact-multiple dims (K % 16 == 0), unguarded.
// AMODE 0: plain A. AMODE 1: A = [ctx | Hj | ctx*Hj] generated on the fly.
template<int AMODE, bool BIAS, bool RELU, bool SCALE>
__global__ __launch_bounds__(128)
void gemm_tc(const float* __restrict__ A, const float* __restrict__ B,
             float* __restrict__ C, int K, int lda, int ldb, int ldc,
             const float* __restrict__ bias, const float* __restrict__ alpha_ptr,
             long sA, long sB, long sC,
             const float* __restrict__ Actx, const float* __restrict__ Ahj)
{
    __shared__ uint As[2][64][20];   // [buf][row][k], stride 20
    __shared__ uint Bs[2][16][72];   // [buf][k][n],  stride 72

    const int bz = blockIdx.z;
    if (AMODE == 0) A += (long)bz * sA;
    B += (long)bz * sB;  C += (long)bz * sC;

    const int tid = threadIdx.x;
    const int wid = tid >> 5, lane = tid & 31;
    const int wm = wid & 1, wn = wid >> 1;      // warp: rows wm*32, cols wn*32
    const int g = lane >> 2, tig = lane & 3;
    const int row0 = blockIdx.y * 64;
    const int col0 = blockIdx.x * 64;

    float acc[2][4][4];
    #pragma unroll
    for (int mt = 0; mt < 2; ++mt)
        #pragma unroll
        for (int nt = 0; nt < 4; ++nt)
            #pragma unroll
            for (int i = 0; i < 4; ++i) acc[mt][nt][i] = 0.f;

    uint4 pa[2], pb[2];

    auto loadA = [&](int kt) {
        #pragma unroll
        for (int u = 0; u < 2; ++u) {
            int lin = tid + u * 128;
            int r = lin >> 2, kc = lin & 3;
            int gk = kt + kc * 4;
            float4 v;
            if (AMODE == 0) {
                v = *(const float4*)&A[(long)(row0 + r) * lda + gk];
            } else {
                long ridx = (long)(row0 + r) * HD;
                if (gk < HD) {
                    v = *(const float4*)&Actx[ridx + gk];
                } else if (gk < 2 * HD) {
                    v = *(const float4*)&Ahj[ridx + gk - HD];
                } else {
                    float4 c4 = *(const float4*)&Actx[ridx + gk - 2 * HD];
                    float4 h4 = *(const float4*)&Ahj[ridx + gk - 2 * HD];
                    v.x = c4.x * h4.x; v.y = c4.y * h4.y;
                    v.z = c4.z * h4.z; v.w = c4.w * h4.w;
                }
            }
            pa[u].x = f2tf(v.x); pa[u].y = f2tf(v.y);
            pa[u].z = f2tf(v.z); pa[u].w = f2tf(v.w);
        }
    };
    auto loadB = [&](int kt) {
        #pragma unroll
        for (int u = 0; u < 2; ++u) {
            int lin = tid + u * 128;
            int k = lin >> 4, n4 = lin & 15;
            float4 v = *(const float4*)&B[(long)(kt + k) * ldb + col0 + n4 * 4];
            pb[u].x = f2tf(v.x); pb[u].y = f2tf(v.y);
            pb[u].z = f2tf(v.z); pb[u].w = f2tf(v.w);
        }
    };
    auto storeT = [&](int buf) {
        #pragma unroll
        for (int u = 0; u < 2; ++u) {
            int lin = tid + u * 128;
            int r = lin >> 2, kc = lin & 3;
            As[buf][r][kc * 4 + 0] = pa[u].x;
            As[buf][r][kc * 4 + 1] = pa[u].y;
            As[buf][r][kc * 4 + 2] = pa[u].z;
            As[buf][r][kc * 4 + 3] = pa[u].w;
            int k = lin >> 4, n4 = lin & 15;
            Bs[buf][k][n4 * 4 + 0] = pb[u].x;
            Bs[buf][k][n4 * 4 + 1] = pb[u].y;
            Bs[buf][k][n4 * 4 + 2] = pb[u].z;
            Bs[buf][k][n4 * 4 + 3] = pb[u].w;
        }
    };

    loadA(0); loadB(0);
    storeT(0);
    __syncthreads();

    int cur = 0;
    for (int kt = 0; kt < K; kt += 16) {
        const bool more = (kt + 16) < K;
        if (more) { loadA(kt + 16); loadB(kt + 16); }

        #pragma unroll
        for (int ks = 0; ks < 2; ++ks) {
            uint a[2][4], b[4][2];
            #pragma unroll
            for (int mt = 0; mt < 2; ++mt) {
                int r = wm * 32 + mt * 16 + g;
                a[mt][0] = As[cur][r][ks * 8 + tig];
                a[mt][1] = As[cur][r + 8][ks * 8 + tig];
                a[mt][2] = As[cur][r][ks * 8 + tig + 4];
                a[mt][3] = As[cur][r + 8][ks * 8 + tig + 4];
            }
            #pragma unroll
            for (int nt = 0; nt < 4; ++nt) {
                int n = wn * 32 + nt * 8 + g;
                b[nt][0] = Bs[cur][ks * 8 + tig][n];
                b[nt][1] = Bs[cur][ks * 8 + tig + 4][n];
            }
            #pragma unroll
            for (int mt = 0; mt < 2; ++mt)
                #pragma unroll
                for (int nt = 0; nt < 4; ++nt)
                    mma_tf32(acc[mt][nt], a[mt], b[nt]);
        }

        if (more) storeT(cur ^ 1);
        __syncthreads();
        if (more) cur ^= 1;
    }

    float alpha = 1.f;
    if (SCALE) alpha = *alpha_ptr;

    #pragma unroll
    for (int mt = 0; mt < 2; ++mt) {
        int r = row0 + wm * 32 + mt * 16 + g;
        #pragma unroll
        for (int nt = 0; nt < 4; ++nt) {
            int c = col0 + wn * 32 + nt * 8 + 2 * tig;
            float b0 = 0.f, b1 = 0.f;
            if (BIAS) { b0 = bias[c]; b1 = bias[c + 1]; }
            float v0 = acc[mt][nt][0] + b0;
            float v1 = acc[mt][nt][1] + b1;
            float v2 = acc[mt][nt][2] + b0;
            float v3 = acc[mt][nt][3] + b1;
            if (RELU) {
                v0 = fmaxf(v0, 0.f); v1 = fmaxf(v1, 0.f);
                v2 = fmaxf(v2, 0.f); v3 = fmaxf(v3, 0.f);
            }
            v0 *= alpha; v1 *= alpha; v2 *= alpha; v3 *= alpha;
            float2 lo = make_float2(v0, v1);
            float2 hi = make_float2(v2, v3);
            *(float2*)&C[(long)r * ldc + c] = lo;
            *(float2*)&C[(long)(r + 8) * ldc + c] = hi;
        }
    }
}

// ---------------- pairwise v4 (R9, frozen): per-block folded weights ----------------
__global__ __launch_bounds__(128)
void pairwise_kernel(const float* __restrict__ Zj, const float* __restrict__ Zi,
                     const float* __restrict__ tjb,
                     const float* __restrict__ Ws1, const float* __restrict__ ws2,
                     const float* __restrict__ bs2, const int* __restrict__ attn_mask,
                     float* __restrict__ probs)
{
    __shared__ float Wc_s[48][96];
    __shared__ float Gs[48][128];
    __shared__ float logits_s[512];
    __shared__ float Zjp_s[24];
    __shared__ float tjb_s[96];
    __shared__ float ws2_s[96];
    __shared__ float red_s[8];

    const int tid = threadIdx.x;
    const int tx = tid & 7;
    const int ty = tid >> 3;
    const int pg = blockIdx.x;
    const int b = pg >> 9;

    if (tid < 24) Zjp_s[tid] = Zj[pg * 24 + tid];
    if (tid < 96) { tjb_s[tid] = tjb[pg * 96 + tid]; ws2_s[tid] = ws2[tid]; }
    __syncthreads();

    for (int idx = tid; idx < 24 * 96; idx += 128) {
        int d = idx / 96, m = idx - d * 96;
        Wc_s[d][m]      = fmaf(Zjp_s[d], Ws1[(48 + d) * 96 + m], Ws1[(24 + d) * 96 + m]);
        Wc_s[24 + d][m] = Ws1[(72 + d) * 96 + m];
    }
    __syncthreads();

    #pragma unroll 1
    for (int qt = 0; qt < 4; ++qt) {
        const int q0 = qt * 128;
        {
            const int q = tid;
            const float* zrow = &Zi[((long)(b * 512 + q0 + q)) * 24];
            float4 z4[6];
            #pragma unroll
            for (int u = 0; u < 6; ++u) z4[u] = *(const float4*)&zrow[u * 4];
            const float zv[24] = {z4[0].x, z4[0].y, z4[0].z, z4[0].w,
                                  z4[1].x, z4[1].y, z4[1].z, z4[1].w,
                                  z4[2].x, z4[2].y, z4[2].z, z4[2].w,
                                  z4[3].x, z4[3].y, z4[3].z, z4[3].w,
                                  z4[4].x, z4[4].y, z4[4].z, z4[4].w,
                                  z4[5].x, z4[5].y, z4[5].z, z4[5].w};
            #pragma unroll
            for (int d = 0; d < 24; ++d) {
                Gs[d][q]      = zv[d];
                Gs[24 + d][q] = fabsf(Zjp_s[d] - zv[d]);
            }
        }
        __syncthreads();

        ull acc[8][6];
        #pragma unroll
        for (int i = 0; i < 8; ++i)
            #pragma unroll
            for (int j = 0; j < 6; ++j) acc[i][j] = 0ull;

        #pragma unroll
        for (int k = 0; k < 48; ++k) {
            float4 g0 = *(const float4*)&Gs[k][ty * 8];
            float4 g1 = *(const float4*)&Gs[k][ty * 8 + 4];
            ulonglong2 w0 = *(const ulonglong2*)&Wc_s[k][tx * 12];
            ulonglong2 w1 = *(const ulonglong2*)&Wc_s[k][tx * 12 + 4];
            ulonglong2 w2 = *(const ulonglong2*)&Wc_s[k][tx * 12 + 8];
            ull gp[8];
            gp[0] = pk2(g0.x); gp[1] = pk2(g0.y); gp[2] = pk2(g0.z); gp[3] = pk2(g0.w);
            gp[4] = pk2(g1.x); gp[5] = pk2(g1.y); gp[6] = pk2(g1.z); gp[7] = pk2(g1.w);
            #pragma unroll
            for (int i = 0; i < 8; ++i) {
                fma2(acc[i][0], gp[i], w0.x);
                fma2(acc[i][1], gp[i], w0.y);
                fma2(acc[i][2], gp[i], w1.x);
                fma2(acc[i][3], gp[i], w1.y);
                fma2(acc[i][4], gp[i], w2.x);
                fma2(acc[i][5], gp[i], w2.y);
            }
        }

        #pragma unroll
        for (int i = 0; i < 8; ++i) {
            int q = ty * 8 + i;
            float s = 0.f;
            #pragma unroll
            for (int j = 0; j < 6; ++j) {
                int m = tx * 12 + 2 * j;
                float2 a = up2(acc[i][j]);
                float h0 = fmaxf(a.x + tjb_s[m], 0.f);
                float h1 = fmaxf(a.y + tjb_s[m + 1], 0.f);
                s = fmaf(h0, ws2_s[m], s);
                s = fmaf(h1, ws2_s[m + 1], s);
            }
            s += __shfl_xor_sync(0xffffffffu, s, 1);
            s += __shfl_xor_sync(0xffffffffu, s, 2);
            s += __shfl_xor_sync(0xffffffffu, s, 4);
            if (tx == 0) logits_s[q0 + q] = s;
        }
        __syncthreads();
    }

    const float bs2v = *bs2;
    #pragma unroll
    for (int q = tid; q < 512; q += 128) {
        float mv = (float)attn_mask[b * 512 + q];
        logits_s[q] += bs2v + (1.f - mv) * (-3.402823466e38f);
    }
    __syncthreads();

    const int wid = tid >> 5, lane = tid & 31;
    float lmax = -INFINITY;
    #pragma unroll
    for (int q = tid; q < 512; q += 128) lmax = fmaxf(lmax, logits_s[q]);
    #pragma unroll
    for (int o = 16; o > 0; o >>= 1) lmax = fmaxf(lmax, __shfl_xor_sync(0xffffffffu, lmax, o));
    if (lane == 0) red_s[wid] = lmax;
    __syncthreads();
    lmax = fmaxf(fmaxf(red_s[0], red_s[1]), fmaxf(red_s[2], red_s[3]));

    float lsum = 0.f;
    float ev[4];
    #pragma unroll
    for (int u = 0; u < 4; ++u) {
        int q = tid + u * 128;
        ev[u] = expf(logits_s[q] - lmax);
        lsum += ev[u];
    }
    #pragma unroll
    for (int o = 16; o > 0; o >>= 1) lsum += __shfl_xor_sync(0xffffffffu, lsum, o);
    if (lane == 0) red_s[4 + wid] = lsum;
    __syncthreads();
    const float inv = 1.f / (red_s[4] + red_s[5] + red_s[6] + red_s[7]);
    #pragma unroll
    for (int u = 0; u < 4; ++u) {
        int q = tid + u * 128;
        probs[(long)pg * 512 + q] = ev[u] * inv;
    }
}

// ---------------- launch ----------------
extern "C" void kernel_launch(void* const* d_in, const int* in_sizes, int n_in,
                              void* d_out, int out_size)
{
    const float* Hj   = (const float*)d_in[0];
    const float* Hi   = (const float*)d_in[1];
    const float* Wpj  = (const float*)d_in[2];
    const float* Wpi  = (const float*)d_in[3];
    const float* Ws1  = (const float*)d_in[4];
    const float* bs1  = (const float*)d_in[5];
    const float* ws2  = (const float*)d_in[6];
    const float* bs2  = (const float*)d_in[7];
    const float* Wv1  = (const float*)d_in[8];
    const float* bv1  = (const float*)d_in[9];
    const float* Wv2  = (const float*)d_in[10];
    const float* bv2  = (const float*)d_in[11];
    const float* alpha= (const float*)d_in[12];
    const int*   mask = (const int*)d_in[13];
    float* out = (float*)d_out;

    float *Zj, *Zi, *tjb, *probs, *ctx, *mhid;
    cudaGetSymbolAddress((void**)&Zj, g_Zj);
    cudaGetSymbolAddress((void**)&Zi, g_Zi);
    cudaGetSymbolAddress((void**)&tjb, g_tjb);
    cudaGetSymbolAddress((void**)&probs, g_probs);
    cudaGetSymbolAddress((void**)&ctx, g_ctx);
    cudaGetSymbolAddress((void**)&mhid, g_mhid);

    // Zj = H_j @ Wpj ; Zi = H_i @ Wpi   (2048 x 24, K=768), batched
    sgemm_small2<<<dim3(1, ROWS/64, 2), 256>>>(
        Hj, Wpj, Zj, nullptr, Hi, Wpi, Zi, nullptr,
        ROWS, DD, HD, HD, DD, DD);

    // tjb = Zj @ Ws1[0:24] + bs1   (2048 x 96, K=24)
    sgemm_small2<<<dim3(2, ROWS/64, 1), 256>>>(
        Zj, Ws1, tjb, bs1, nullptr, nullptr, nullptr, nullptr,
        ROWS, MMDIM, DD, DD, MMDIM, MMDIM);

    // fused pairwise logits + softmax -> probs
    pairwise_kernel<<<ROWS, 128>>>(Zj, Zi, tjb, Ws1, ws2, bs2, mask, probs);

    // ctx = probs @ H_i   (batched 4x: 512 x 768, K=512) — tf32 tensor cores
    gemm_tc<0,false,false,false><<<dim3(HD/64, SEQ/64, BATCH), 128>>>(
        probs, Hi, ctx, SEQ, SEQ, HD, HD, nullptr, nullptr,
        (long)SEQ*SEQ, (long)SEQ*HD, (long)SEQ*HD, nullptr, nullptr);

    // mhid = relu([ctx|Hj|ctx*Hj] @ Wv1 + bv1)   (2048 x 768, K=2304; X fused)
    gemm_tc<1,true,true,false><<<dim3(OO/64, ROWS/64, 1), 128>>>(
        nullptr, Wv1, mhid, XCOLS, 0, OO, OO, bv1, nullptr,
        0, 0, 0, ctx, Hj);

    // out = alpha * (mhid @ Wv2 + bv2)   (2048 x 768, K=768)
    gemm_tc<0,true,false,true><<<dim3(HD/64, ROWS/64, 1), 128>>>(
        mhid, Wv2, out, OO, OO, HD, HD, bv2, alpha,
        0, 0, 0, nullptr, nullptr);
}

// round 11
// speedup vs baseline: 2.4900x; 1.0792x over previous
#include <cuda_runtime.h>
#include <math.h>

#define BATCH 4
#define SEQ   512
#define HD    768
#define DD    24
#define MMDIM 96
#define OO    768
#define ROWS  (BATCH*SEQ)       // 2048
#define XCOLS (3*HD)            // 2304

typedef unsigned long long ull;
typedef unsigned int uint;

// ---------------- scratch (no allocations allowed) ----------------
__device__ float g_Zj[ROWS*DD];
__device__ float g_Zi[ROWS*DD];
__device__ float g_tjb[ROWS*MMDIM];
__device__ float g_probs[(long)BATCH*SEQ*SEQ];
__device__ float g_ctx[(long)ROWS*HD];
__device__ float g_mhid[(long)ROWS*OO];

// ---------------- packed f32x2 helpers ----------------
__device__ __forceinline__ ull pk2(float x) {
    ull r; asm("mov.b64 %0, {%1, %1};" : "=l"(r) : "f"(x)); return r;
}
__device__ __forceinline__ void fma2(ull &d, ull a, ull b) {
    asm("fma.rn.f32x2 %0, %1, %2, %0;" : "+l"(d) : "l"(a), "l"(b));
}
__device__ __forceinline__ float2 up2(ull v) {
    float2 r; asm("mov.b64 {%0, %1}, %2;" : "=f"(r.x), "=f"(r.y) : "l"(v)); return r;
}

// ---------------- tf32 helpers ----------------
__device__ __forceinline__ uint f2tf(float x) {
    uint r; asm("cvt.rna.tf32.f32 %0, %1;" : "=r"(r) : "f"(x)); return r;
}
__device__ __forceinline__ void mma_tf32(float* c, const uint* a, const uint* b) {
    asm volatile(
        "mma.sync.aligned.m16n8k8.row.col.f32.tf32.tf32.f32 "
        "{%0,%1,%2,%3}, {%4,%5,%6,%7}, {%8,%9}, {%0,%1,%2,%3};"
        : "+f"(c[0]), "+f"(c[1]), "+f"(c[2]), "+f"(c[3])
        : "r"(a[0]), "r"(a[1]), "r"(a[2]), "r"(a[3]), "r"(b[0]), "r"(b[1]));
}

// ---------------- small generic SGEMM, z-batched over pointer pairs ----------------
__global__ __launch_bounds__(256)
void sgemm_small2(const float* __restrict__ A0, const float* __restrict__ B0,
                  float* __restrict__ C0, const float* __restrict__ bias0,
                  const float* __restrict__ A1, const float* __restrict__ B1,
                  float* __restrict__ C1, const float* __restrict__ bias1,
                  int M, int N, int K, int lda, int ldb, int ldc)
{
    __shared__ float As[16][64];
    __shared__ float Bs[16][64];
    const float* A = blockIdx.z ? A1 : A0;
    const float* B = blockIdx.z ? B1 : B0;
    float*       C = blockIdx.z ? C1 : C0;
    const float* bias = blockIdx.z ? bias1 : bias0;

    const int tid = threadIdx.x;
    const int tx = tid & 15, ty = tid >> 4;
    const int row0 = blockIdx.y * 64;
    const int col0 = blockIdx.x * 64;

    float acc[4][4] = {};
    for (int k0 = 0; k0 < K; k0 += 16) {
        #pragma unroll
        for (int u = 0; u < 4; ++u) {
            int t = tid + u * 256;
            int r = t >> 4, kk = t & 15;
            int gr = row0 + r, gk = k0 + kk;
            float v = 0.f;
            if (gr < M && gk < K) v = A[(long)gr * lda + gk];
            As[kk][r] = v;
        }
        #pragma unroll
        for (int u = 0; u < 4; ++u) {
            int t = tid + u * 256;
            int kk = t >> 6, n = t & 63;
            int gk = k0 + kk, gn = col0 + n;
            float v = 0.f;
            if (gk < K && gn < N) v = B[(long)gk * ldb + gn];
            Bs[kk][n] = v;
        }
        __syncthreads();
        #pragma unroll
        for (int kk = 0; kk < 16; ++kk) {
            float4 a4 = *(const float4*)&As[kk][ty * 4];
            float4 b4 = *(const float4*)&Bs[kk][tx * 4];
            float a[4] = {a4.x, a4.y, a4.z, a4.w};
            float b[4] = {b4.x, b4.y, b4.z, b4.w};
            #pragma unroll
            for (int i = 0; i < 4; ++i)
                #pragma unroll
                for (int j = 0; j < 4; ++j)
                    acc[i][j] = fmaf(a[i], b[j], acc[i][j]);
        }
        __syncthreads();
    }
    #pragma unroll
    for (int i = 0; i < 4; ++i) {
        int r = row0 + ty * 4 + i;
        if (r >= M) continue;
        #pragma unroll
        for (int j = 0; j < 4; ++j) {
            int c = col0 + tx * 4 + j;
            if (c >= N) continue;
            float v = acc[i][j];
            if (bias) v += bias[c];
            C[(long)r * ldc + c] = v;
        }
    }
}

// ---------------- gemm_tc2: 64x64 tile, 256 threads (8 warps), tf32 mma, ktile=32 ----------------
// Warp tile 16x32: wm = wid&3 (rows wm*16), wn = wid>>2 (cols wn*32); 1 m-frag x 4 n-frags.
// Strides 36/72: all fragment LDS.32 and loader STS.128 phases hit 32 distinct banks.
// Double-buffered, register prefetch, 1 sync/ktile. K % 32 == 0, unguarded.
// AMODE 0: plain A. AMODE 1: A = [ctx | Hj | ctx*Hj] generated on the fly.
template<int AMODE, bool BIAS, bool RELU, bool SCALE>
__global__ __launch_bounds__(256)
void gemm_tc2(const float* __restrict__ A, const float* __restrict__ B,
              float* __restrict__ C, int K, int lda, int ldb, int ldc,
              const float* __restrict__ bias, const float* __restrict__ alpha_ptr,
              long sA, long sB, long sC,
              const float* __restrict__ Actx, const float* __restrict__ Ahj)
{
    __shared__ uint As[2][64][36];   // [buf][row][k], stride 36 (18 KB)
    __shared__ uint Bs[2][32][72];   // [buf][k][n],  stride 72 (18 KB)

    const int bz = blockIdx.z;
    if (AMODE == 0) A += (long)bz * sA;
    B += (long)bz * sB;  C += (long)bz * sC;

    const int tid = threadIdx.x;
    const int wid = tid >> 5, lane = tid & 31;
    const int wm = wid & 3, wn = wid >> 2;      // warp: rows wm*16, cols wn*32
    const int g = lane >> 2, tig = lane & 3;
    const int row0 = blockIdx.y * 64;
    const int col0 = blockIdx.x * 64;

    // loader indices (512 float4 per operand tile, 2 per thread)
    const int ar = tid >> 3, akc = tid & 7;     // A: row, k-chunk of 4
    const int bk = tid >> 4, bn4 = tid & 15;    // B: k-row, n-chunk of 4

    float acc[4][4];
    #pragma unroll
    for (int nt = 0; nt < 4; ++nt)
        #pragma unroll
        for (int i = 0; i < 4; ++i) acc[nt][i] = 0.f;

    uint4 pa[2], pb[2];

    auto loadA = [&](int kt) {
        #pragma unroll
        for (int u = 0; u < 2; ++u) {
            int r = ar + u * 32;
            int gk = kt + akc * 4;
            float4 v;
            if (AMODE == 0) {
                v = *(const float4*)&A[(long)(row0 + r) * lda + gk];
            } else {
                long ridx = (long)(row0 + r) * HD;
                if (gk < HD) {
                    v = *(const float4*)&Actx[ridx + gk];
                } else if (gk < 2 * HD) {
                    v = *(const float4*)&Ahj[ridx + gk - HD];
                } else {
                    float4 c4 = *(const float4*)&Actx[ridx + gk - 2 * HD];
                    float4 h4 = *(const float4*)&Ahj[ridx + gk - 2 * HD];
                    v.x = c4.x * h4.x; v.y = c4.y * h4.y;
                    v.z = c4.z * h4.z; v.w = c4.w * h4.w;
                }
            }
            pa[u].x = f2tf(v.x); pa[u].y = f2tf(v.y);
            pa[u].z = f2tf(v.z); pa[u].w = f2tf(v.w);
        }
    };
    auto loadB = [&](int kt) {
        #pragma unroll
        for (int u = 0; u < 2; ++u) {
            int k = bk + u * 16;
            float4 v = *(const float4*)&B[(long)(kt + k) * ldb + col0 + bn4 * 4];
            pb[u].x = f2tf(v.x); pb[u].y = f2tf(v.y);
            pb[u].z = f2tf(v.z); pb[u].w = f2tf(v.w);
        }
    };
    auto storeT = [&](int buf) {
        #pragma unroll
        for (int u = 0; u < 2; ++u) {
            *(uint4*)&As[buf][ar + u * 32][akc * 4] = pa[u];
            *(uint4*)&Bs[buf][bk + u * 16][bn4 * 4] = pb[u];
        }
    };

    loadA(0); loadB(0);
    storeT(0);
    __syncthreads();

    int cur = 0;
    for (int kt = 0; kt < K; kt += 32) {
        const bool more = (kt + 32) < K;
        if (more) { loadA(kt + 32); loadB(kt + 32); }

        #pragma unroll
        for (int ks = 0; ks < 4; ++ks) {
            uint a[4], b[4][2];
            int r = wm * 16 + g;
            a[0] = As[cur][r][ks * 8 + tig];
            a[1] = As[cur][r + 8][ks * 8 + tig];
            a[2] = As[cur][r][ks * 8 + tig + 4];
            a[3] = As[cur][r + 8][ks * 8 + tig + 4];
            #pragma unroll
            for (int nt = 0; nt < 4; ++nt) {
                int n = wn * 32 + nt * 8 + g;
                b[nt][0] = Bs[cur][ks * 8 + tig][n];
                b[nt][1] = Bs[cur][ks * 8 + tig + 4][n];
            }
            #pragma unroll
            for (int nt = 0; nt < 4; ++nt)
                mma_tf32(acc[nt], a, b[nt]);
        }

        if (more) storeT(cur ^ 1);
        __syncthreads();
        if (more) cur ^= 1;
    }

    float alpha = 1.f;
    if (SCALE) alpha = *alpha_ptr;

    int r = row0 + wm * 16 + g;
    #pragma unroll
    for (int nt = 0; nt < 4; ++nt) {
        int c = col0 + wn * 32 + nt * 8 + 2 * tig;
        float b0 = 0.f, b1 = 0.f;
        if (BIAS) { b0 = bias[c]; b1 = bias[c + 1]; }
        float v0 = acc[nt][0] + b0;
        float v1 = acc[nt][1] + b1;
        float v2 = acc[nt][2] + b0;
        float v3 = acc[nt][3] + b1;
        if (RELU) {
            v0 = fmaxf(v0, 0.f); v1 = fmaxf(v1, 0.f);
            v2 = fmaxf(v2, 0.f); v3 = fmaxf(v3, 0.f);
        }
        v0 *= alpha; v1 *= alpha; v2 *= alpha; v3 *= alpha;
        *(float2*)&C[(long)r * ldc + c] = make_float2(v0, v1);
        *(float2*)&C[(long)(r + 8) * ldc + c] = make_float2(v2, v3);
    }
}

// ---------------- pairwise v4 (R9, frozen): per-block folded weights ----------------
__global__ __launch_bounds__(128)
void pairwise_kernel(const float* __restrict__ Zj, const float* __restrict__ Zi,
                     const float* __restrict__ tjb,
                     const float* __restrict__ Ws1, const float* __restrict__ ws2,
                     const float* __restrict__ bs2, const int* __restrict__ attn_mask,
                     float* __restrict__ probs)
{
    __shared__ float Wc_s[48][96];
    __shared__ float Gs[48][128];
    __shared__ float logits_s[512];
    __shared__ float Zjp_s[24];
    __shared__ float tjb_s[96];
    __shared__ float ws2_s[96];
    __shared__ float red_s[8];

    const int tid = threadIdx.x;
    const int tx = tid & 7;
    const int ty = tid >> 3;
    const int pg = blockIdx.x;
    const int b = pg >> 9;

    if (tid < 24) Zjp_s[tid] = Zj[pg * 24 + tid];
    if (tid < 96) { tjb_s[tid] = tjb[pg * 96 + tid]; ws2_s[tid] = ws2[tid]; }
    __syncthreads();

    for (int idx = tid; idx < 24 * 96; idx += 128) {
        int d = idx / 96, m = idx - d * 96;
        Wc_s[d][m]      = fmaf(Zjp_s[d], Ws1[(48 + d) * 96 + m], Ws1[(24 + d) * 96 + m]);
        Wc_s[24 + d][m] = Ws1[(72 + d) * 96 + m];
    }
    __syncthreads();

    #pragma unroll 1
    for (int qt = 0; qt < 4; ++qt) {
        const int q0 = qt * 128;
        {
            const int q = tid;
            const float* zrow = &Zi[((long)(b * 512 + q0 + q)) * 24];
            float4 z4[6];
            #pragma unroll
            for (int u = 0; u < 6; ++u) z4[u] = *(const float4*)&zrow[u * 4];
            const float zv[24] = {z4[0].x, z4[0].y, z4[0].z, z4[0].w,
                                  z4[1].x, z4[1].y, z4[1].z, z4[1].w,
                                  z4[2].x, z4[2].y, z4[2].z, z4[2].w,
                                  z4[3].x, z4[3].y, z4[3].z, z4[3].w,
                                  z4[4].x, z4[4].y, z4[4].z, z4[4].w,
                                  z4[5].x, z4[5].y, z4[5].z, z4[5].w};
            #pragma unroll
            for (int d = 0; d < 24; ++d) {
                Gs[d][q]      = zv[d];
                Gs[24 + d][q] = fabsf(Zjp_s[d] - zv[d]);
            }
        }
        __syncthreads();

        ull acc[8][6];
        #pragma unroll
        for (int i = 0; i < 8; ++i)
            #pragma unroll
            for (int j = 0; j < 6; ++j) acc[i][j] = 0ull;

        #pragma unroll
        for (int k = 0; k < 48; ++k) {
            float4 g0 = *(const float4*)&Gs[k][ty * 8];
            float4 g1 = *(const float4*)&Gs[k][ty * 8 + 4];
            ulonglong2 w0 = *(const ulonglong2*)&Wc_s[k][tx * 12];
            ulonglong2 w1 = *(const ulonglong2*)&Wc_s[k][tx * 12 + 4];
            ulonglong2 w2 = *(const ulonglong2*)&Wc_s[k][tx * 12 + 8];
            ull gp[8];
            gp[0] = pk2(g0.x); gp[1] = pk2(g0.y); gp[2] = pk2(g0.z); gp[3] = pk2(g0.w);
            gp[4] = pk2(g1.x); gp[5] = pk2(g1.y); gp[6] = pk2(g1.z); gp[7] = pk2(g1.w);
            #pragma unroll
            for (int i = 0; i < 8; ++i) {
                fma2(acc[i][0], gp[i], w0.x);
                fma2(acc[i][1], gp[i], w0.y);
                fma2(acc[i][2], gp[i], w1.x);
                fma2(acc[i][3], gp[i], w1.y);
                fma2(acc[i][4], gp[i], w2.x);
                fma2(acc[i][5], gp[i], w2.y);
            }
        }

        #pragma unroll
        for (int i = 0; i < 8; ++i) {
            int q = ty * 8 + i;
            float s = 0.f;
            #pragma unroll
            for (int j = 0; j < 6; ++j) {
                int m = tx * 12 + 2 * j;
                float2 a = up2(acc[i][j]);
                float h0 = fmaxf(a.x + tjb_s[m], 0.f);
                float h1 = fmaxf(a.y + tjb_s[m + 1], 0.f);
                s = fmaf(h0, ws2_s[m], s);
                s = fmaf(h1, ws2_s[m + 1], s);
            }
            s += __shfl_xor_sync(0xffffffffu, s, 1);
            s += __shfl_xor_sync(0xffffffffu, s, 2);
            s += __shfl_xor_sync(0xffffffffu, s, 4);
            if (tx == 0) logits_s[q0 + q] = s;
        }
        __syncthreads();
    }

    const float bs2v = *bs2;
    #pragma unroll
    for (int q = tid; q < 512; q += 128) {
        float mv = (float)attn_mask[b * 512 + q];
        logits_s[q] += bs2v + (1.f - mv) * (-3.402823466e38f);
    }
    __syncthreads();

    const int wid = tid >> 5, lane = tid & 31;
    float lmax = -INFINITY;
    #pragma unroll
    for (int q = tid; q < 512; q += 128) lmax = fmaxf(lmax, logits_s[q]);
    #pragma unroll
    for (int o = 16; o > 0; o >>= 1) lmax = fmaxf(lmax, __shfl_xor_sync(0xffffffffu, lmax, o));
    if (lane == 0) red_s[wid] = lmax;
    __syncthreads();
    lmax = fmaxf(fmaxf(red_s[0], red_s[1]), fmaxf(red_s[2], red_s[3]));

    float lsum = 0.f;
    float ev[4];
    #pragma unroll
    for (int u = 0; u < 4; ++u) {
        int q = tid + u * 128;
        ev[u] = expf(logits_s[q] - lmax);
        lsum += ev[u];
    }
    #pragma unroll
    for (int o = 16; o > 0; o >>= 1) lsum += __shfl_xor_sync(0xffffffffu, lsum, o);
    if (lane == 0) red_s[4 + wid] = lsum;
    __syncthreads();
    const float inv = 1.f / (red_s[4] + red_s[5] + red_s[6] + red_s[7]);
    #pragma unroll
    for (int u = 0; u < 4; ++u) {
        int q = tid + u * 128;
        probs[(long)pg * 512 + q] = ev[u] * inv;
    }
}

// ---------------- launch ----------------
extern "C" void kernel_launch(void* const* d_in, const int* in_sizes, int n_in,
                              void* d_out, int out_size)
{
    const float* Hj   = (const float*)d_in[0];
    const float* Hi   = (const float*)d_in[1];
    const float* Wpj  = (const float*)d_in[2];
    const float* Wpi  = (const float*)d_in[3];
    const float* Ws1  = (const float*)d_in[4];
    const float* bs1  = (const float*)d_in[5];
    const float* ws2  = (const float*)d_in[6];
    const float* bs2  = (const float*)d_in[7];
    const float* Wv1  = (const float*)d_in[8];
    const float* bv1  = (const float*)d_in[9];
    const float* Wv2  = (const float*)d_in[10];
    const float* bv2  = (const float*)d_in[11];
    const float* alpha= (const float*)d_in[12];
    const int*   mask = (const int*)d_in[13];
    float* out = (float*)d_out;

    float *Zj, *Zi, *tjb, *probs, *ctx, *mhid;
    cudaGetSymbolAddress((void**)&Zj, g_Zj);
    cudaGetSymbolAddress((void**)&Zi, g_Zi);
    cudaGetSymbolAddress((void**)&tjb, g_tjb);
    cudaGetSymbolAddress((void**)&probs, g_probs);
    cudaGetSymbolAddress((void**)&ctx, g_ctx);
    cudaGetSymbolAddress((void**)&mhid, g_mhid);

    // Zj = H_j @ Wpj ; Zi = H_i @ Wpi   (2048 x 24, K=768), batched
    sgemm_small2<<<dim3(1, ROWS/64, 2), 256>>>(
        Hj, Wpj, Zj, nullptr, Hi, Wpi, Zi, nullptr,
        ROWS, DD, HD, HD, DD, DD);

    // tjb = Zj @ Ws1[0:24] + bs1   (2048 x 96, K=24)
    sgemm_small2<<<dim3(2, ROWS/64, 1), 256>>>(
        Zj, Ws1, tjb, bs1, nullptr, nullptr, nullptr, nullptr,
        ROWS, MMDIM, DD, DD, MMDIM, MMDIM);

    // fused pairwise logits + softmax -> probs
    pairwise_kernel<<<ROWS, 128>>>(Zj, Zi, tjb, Ws1, ws2, bs2, mask, probs);

    // ctx = probs @ H_i   (batched 4x: 512 x 768, K=512) — tf32 tensor cores
    gemm_tc2<0,false,false,false><<<dim3(HD/64, SEQ/64, BATCH), 256>>>(
        probs, Hi, ctx, SEQ, SEQ, HD, HD, nullptr, nullptr,
        (long)SEQ*SEQ, (long)SEQ*HD, (long)SEQ*HD, nullptr, nullptr);

    // mhid = relu([ctx|Hj|ctx*Hj] @ Wv1 + bv1)   (2048 x 768, K=2304; X fused)
    gemm_tc2<1,true,true,false><<<dim3(OO/64, ROWS/64, 1), 256>>>(
        nullptr, Wv1, mhid, XCOLS, 0, OO, OO, bv1, nullptr,
        0, 0, 0, ctx, Hj);

    // out = alpha * (mhid @ Wv2 + bv2)   (2048 x 768, K=768)
    gemm_tc2<0,true,false,true><<<dim3(HD/64, ROWS/64, 1), 256>>>(
        mhid, Wv2, out, OO, OO, HD, HD, bv2, alpha,
        0, 0, 0, nullptr, nullptr);
}

// round 13
// speedup vs baseline: 2.7184x; 1.0917x over previous
#include <cuda_runtime.h>
#include <math.h>

#define BATCH 4
#define SEQ   512
#define HD    768
#define DD    24
#define MMDIM 96
#define OO    768
#define ROWS  (BATCH*SEQ)       // 2048
#define XCOLS (3*HD)            // 2304

typedef unsigned long long ull;
typedef unsigned int uint;

// ---------------- scratch (no allocations allowed) ----------------
__device__ float g_Zj[ROWS*DD];
__device__ float g_Zi[ROWS*DD];
__device__ float g_tjb[ROWS*MMDIM];
__device__ float g_probs[(long)BATCH*SEQ*SEQ];
__device__ float g_ctx[(long)ROWS*HD];
__device__ float g_mhid[(long)ROWS*OO];

// ---------------- tf32 helpers ----------------
__device__ __forceinline__ uint f2tf(float x) {
    uint r; asm("cvt.rna.tf32.f32 %0, %1;" : "=r"(r) : "f"(x)); return r;
}
__device__ __forceinline__ void mma_tf32(float* c, const uint* a, const uint* b) {
    asm volatile(
        "mma.sync.aligned.m16n8k8.row.col.f32.tf32.tf32.f32 "
        "{%0,%1,%2,%3}, {%4,%5,%6,%7}, {%8,%9}, {%0,%1,%2,%3};"
        : "+f"(c[0]), "+f"(c[1]), "+f"(c[2]), "+f"(c[3])
        : "r"(a[0]), "r"(a[1]), "r"(a[2]), "r"(a[3]), "r"(b[0]), "r"(b[1]));
}

// ---------------- small generic SGEMM, z-batched over pointer pairs ----------------
__global__ __launch_bounds__(256)
void sgemm_small2(const float* __restrict__ A0, const float* __restrict__ B0,
                  float* __restrict__ C0, const float* __restrict__ bias0,
                  const float* __restrict__ A1, const float* __restrict__ B1,
                  float* __restrict__ C1, const float* __restrict__ bias1,
                  int M, int N, int K, int lda, int ldb, int ldc)
{
    __shared__ float As[16][64];
    __shared__ float Bs[16][64];
    const float* A = blockIdx.z ? A1 : A0;
    const float* B = blockIdx.z ? B1 : B0;
    float*       C = blockIdx.z ? C1 : C0;
    const float* bias = blockIdx.z ? bias1 : bias0;

    const int tid = threadIdx.x;
    const int tx = tid & 15, ty = tid >> 4;
    const int row0 = blockIdx.y * 64;
    const int col0 = blockIdx.x * 64;

    float acc[4][4] = {};
    for (int k0 = 0; k0 < K; k0 += 16) {
        #pragma unroll
        for (int u = 0; u < 4; ++u) {
            int t = tid + u * 256;
            int r = t >> 4, kk = t & 15;
            int gr = row0 + r, gk = k0 + kk;
            float v = 0.f;
            if (gr < M && gk < K) v = A[(long)gr * lda + gk];
            As[kk][r] = v;
        }
        #pragma unroll
        for (int u = 0; u < 4; ++u) {
            int t = tid + u * 256;
            int kk = t >> 6, n = t & 63;
            int gk = k0 + kk, gn = col0 + n;
            float v = 0.f;
            if (gk < K && gn < N) v = B[(long)gk * ldb + gn];
            Bs[kk][n] = v;
        }
        __syncthreads();
        #pragma unroll
        for (int kk = 0; kk < 16; ++kk) {
            float4 a4 = *(const float4*)&As[kk][ty * 4];
            float4 b4 = *(const float4*)&Bs[kk][tx * 4];
            float a[4] = {a4.x, a4.y, a4.z, a4.w};
            float b[4] = {b4.x, b4.y, b4.z, b4.w};
            #pragma unroll
            for (int i = 0; i < 4; ++i)
                #pragma unroll
                for (int j = 0; j < 4; ++j)
                    acc[i][j] = fmaf(a[i], b[j], acc[i][j]);
        }
        __syncthreads();
    }
    #pragma unroll
    for (int i = 0; i < 4; ++i) {
        int r = row0 + ty * 4 + i;
        if (r >= M) continue;
        #pragma unroll
        for (int j = 0; j < 4; ++j) {
            int c = col0 + tx * 4 + j;
            if (c >= N) continue;
            float v = acc[i][j];
            if (bias) v += bias[c];
            C[(long)r * ldc + c] = v;
        }
    }
}

// ---------------- gemm_tc2 (R11, frozen): 64x64 tile, 256 threads, tf32 mma ----------------
template<int AMODE, bool BIAS, bool RELU, bool SCALE>
__global__ __launch_bounds__(256)
void gemm_tc2(const float* __restrict__ A, const float* __restrict__ B,
              float* __restrict__ C, int K, int lda, int ldb, int ldc,
              const float* __restrict__ bias, const float* __restrict__ alpha_ptr,
              long sA, long sB, long sC,
              const float* __restrict__ Actx, const float* __restrict__ Ahj)
{
    __shared__ uint As[2][64][36];
    __shared__ uint Bs[2][32][72];

    const int bz = blockIdx.z;
    if (AMODE == 0) A += (long)bz * sA;
    B += (long)bz * sB;  C += (long)bz * sC;

    const int tid = threadIdx.x;
    const int wid = tid >> 5, lane = tid & 31;
    const int wm = wid & 3, wn = wid >> 2;
    const int g = lane >> 2, tig = lane & 3;
    const int row0 = blockIdx.y * 64;
    const int col0 = blockIdx.x * 64;

    const int ar = tid >> 3, akc = tid & 7;
    const int bk = tid >> 4, bn4 = tid & 15;

    float acc[4][4];
    #pragma unroll
    for (int nt = 0; nt < 4; ++nt)
        #pragma unroll
        for (int i = 0; i < 4; ++i) acc[nt][i] = 0.f;

    uint4 pa[2], pb[2];

    auto loadA = [&](int kt) {
        #pragma unroll
        for (int u = 0; u < 2; ++u) {
            int r = ar + u * 32;
            int gk = kt + akc * 4;
            float4 v;
            if (AMODE == 0) {
                v = *(const float4*)&A[(long)(row0 + r) * lda + gk];
            } else {
                long ridx = (long)(row0 + r) * HD;
                if (gk < HD) {
                    v = *(const float4*)&Actx[ridx + gk];
                } else if (gk < 2 * HD) {
                    v = *(const float4*)&Ahj[ridx + gk - HD];
                } else {
                    float4 c4 = *(const float4*)&Actx[ridx + gk - 2 * HD];
                    float4 h4 = *(const float4*)&Ahj[ridx + gk - 2 * HD];
                    v.x = c4.x * h4.x; v.y = c4.y * h4.y;
                    v.z = c4.z * h4.z; v.w = c4.w * h4.w;
                }
            }
            pa[u].x = f2tf(v.x); pa[u].y = f2tf(v.y);
            pa[u].z = f2tf(v.z); pa[u].w = f2tf(v.w);
        }
    };
    auto loadB = [&](int kt) {
        #pragma unroll
        for (int u = 0; u < 2; ++u) {
            int k = bk + u * 16;
            float4 v = *(const float4*)&B[(long)(kt + k) * ldb + col0 + bn4 * 4];
            pb[u].x = f2tf(v.x); pb[u].y = f2tf(v.y);
            pb[u].z = f2tf(v.z); pb[u].w = f2tf(v.w);
        }
    };
    auto storeT = [&](int buf) {
        #pragma unroll
        for (int u = 0; u < 2; ++u) {
            *(uint4*)&As[buf][ar + u * 32][akc * 4] = pa[u];
            *(uint4*)&Bs[buf][bk + u * 16][bn4 * 4] = pb[u];
        }
    };

    loadA(0); loadB(0);
    storeT(0);
    __syncthreads();

    int cur = 0;
    for (int kt = 0; kt < K; kt += 32) {
        const bool more = (kt + 32) < K;
        if (more) { loadA(kt + 32); loadB(kt + 32); }

        #pragma unroll
        for (int ks = 0; ks < 4; ++ks) {
            uint a[4], b[4][2];
            int r = wm * 16 + g;
            a[0] = As[cur][r][ks * 8 + tig];
            a[1] = As[cur][r + 8][ks * 8 + tig];
            a[2] = As[cur][r][ks * 8 + tig + 4];
            a[3] = As[cur][r + 8][ks * 8 + tig + 4];
            #pragma unroll
            for (int nt = 0; nt < 4; ++nt) {
                int n = wn * 32 + nt * 8 + g;
                b[nt][0] = Bs[cur][ks * 8 + tig][n];
                b[nt][1] = Bs[cur][ks * 8 + tig + 4][n];
            }
            #pragma unroll
            for (int nt = 0; nt < 4; ++nt)
                mma_tf32(acc[nt], a, b[nt]);
        }

        if (more) storeT(cur ^ 1);
        __syncthreads();
        if (more) cur ^= 1;
    }

    float alpha = 1.f;
    if (SCALE) alpha = *alpha_ptr;

    int r = row0 + wm * 16 + g;
    #pragma unroll
    for (int nt = 0; nt < 4; ++nt) {
        int c = col0 + wn * 32 + nt * 8 + 2 * tig;
        float b0 = 0.f, b1 = 0.f;
        if (BIAS) { b0 = bias[c]; b1 = bias[c + 1]; }
        float v0 = acc[nt][0] + b0;
        float v1 = acc[nt][1] + b1;
        float v2 = acc[nt][2] + b0;
        float v3 = acc[nt][3] + b1;
        if (RELU) {
            v0 = fmaxf(v0, 0.f); v1 = fmaxf(v1, 0.f);
            v2 = fmaxf(v2, 0.f); v3 = fmaxf(v3, 0.f);
        }
        v0 *= alpha; v1 *= alpha; v2 *= alpha; v3 *= alpha;
        *(float2*)&C[(long)r * ldc + c] = make_float2(v0, v1);
        *(float2*)&C[(long)(r + 8) * ldc + c] = make_float2(v2, v3);
    }
}

// ---------------- pairwise v6: 3xTF32 split (near-fp32) tensor cores ----------------
// One block per p (128 thr, 4 warps). B = folded weights [W'|W1d], pre-split big/res
// in smem (stride 104, conflict-free). A per q-tile of 128: G = [Zi | |zjp-Zi|] fp32
// in smem (stride 52, conflict-free); fragments split big/res in registers.
// acc += Ares*Bbig + Abig*Bres + Abig*Bbig  (3 mma) — error ~2^-21.
#define PW6_WB_OFF   0                        // Wbig [48][104] uint
#define PW6_WR_OFF   (48*104)                 // Wres [48][104] uint
#define PW6_G_OFF    (PW6_WR_OFF + 48*104)    // G fp32 [128][52]
#define PW6_LOG_OFF  (PW6_G_OFF + 128*52)     // 512 float
#define PW6_TJB_OFF  (PW6_LOG_OFF + 512)
#define PW6_WS2_OFF  (PW6_TJB_OFF + 96)
#define PW6_ZJP_OFF  (PW6_WS2_OFF + 96)
#define PW6_RED_OFF  (PW6_ZJP_OFF + 24)
#define PW6_WORDS    (PW6_RED_OFF + 8)
#define PW6_BYTES    (PW6_WORDS * 4)          // ~69.5 KB

__global__ __launch_bounds__(128)
void pairwise_tc3(const float* __restrict__ Zj, const float* __restrict__ Zi,
                  const float* __restrict__ tjb,
                  const float* __restrict__ Ws1, const float* __restrict__ ws2,
                  const float* __restrict__ bs2, const int* __restrict__ attn_mask,
                  float* __restrict__ probs)
{
    extern __shared__ uint dynU[];
    uint*  Wbig     = dynU + PW6_WB_OFF;
    uint*  Wres     = dynU + PW6_WR_OFF;
    float* GsF      = (float*)(dynU + PW6_G_OFF);
    float* logits_s = (float*)(dynU + PW6_LOG_OFF);
    float* tjb_s    = (float*)(dynU + PW6_TJB_OFF);
    float* ws2_s    = (float*)(dynU + PW6_WS2_OFF);
    float* Zjp_s    = (float*)(dynU + PW6_ZJP_OFF);
    float* red_s    = (float*)(dynU + PW6_RED_OFF);

    const int tid = threadIdx.x;
    const int wid = tid >> 5, lane = tid & 31;
    const int g = lane >> 2, tig = lane & 3;
    const int pg = blockIdx.x;
    const int b = pg >> 9;

    if (tid < 24) Zjp_s[tid] = Zj[pg * 24 + tid];
    if (tid < 96) { tjb_s[tid] = tjb[pg * 96 + tid]; ws2_s[tid] = ws2[tid]; }
    __syncthreads();

    // Build folded weights, split into big/res.
    for (int idx = tid; idx < 24 * 96; idx += 128) {
        int d = idx / 96, m = idx - d * 96;
        float wp = fmaf(Zjp_s[d], Ws1[(48 + d) * 96 + m], Ws1[(24 + d) * 96 + m]);
        uint bp = f2tf(wp);
        Wbig[d * 104 + m] = bp;
        Wres[d * 104 + m] = f2tf(wp - __uint_as_float(bp));
        float wd = Ws1[(72 + d) * 96 + m];
        uint bd = f2tf(wd);
        Wbig[(24 + d) * 104 + m] = bd;
        Wres[(24 + d) * 104 + m] = f2tf(wd - __uint_as_float(bd));
    }
    __syncthreads();

    #pragma unroll 1
    for (int qt = 0; qt < 4; ++qt) {
        const int q0 = qt * 128;

        // Build G tile: one thread per q row, fp32, float4 stores (conflict-free).
        {
            const int q = tid;
            const float* zrow = &Zi[((long)(b * 512 + q0 + q)) * 24];
            float4 z4[6];
            #pragma unroll
            for (int u = 0; u < 6; ++u) z4[u] = *(const float4*)&zrow[u * 4];
            float* dst = &GsF[q * 52];
            #pragma unroll
            for (int u = 0; u < 6; ++u) *(float4*)&dst[u * 4] = z4[u];
            #pragma unroll
            for (int u = 0; u < 6; ++u) {
                float4 dv;
                dv.x = fabsf(Zjp_s[u*4+0] - z4[u].x);
                dv.y = fabsf(Zjp_s[u*4+1] - z4[u].y);
                dv.z = fabsf(Zjp_s[u*4+2] - z4[u].z);
                dv.w = fabsf(Zjp_s[u*4+3] - z4[u].w);
                *(float4*)&dst[24 + u * 4] = dv;
            }
        }
        __syncthreads();

        float acc[2][12][4];
        #pragma unroll
        for (int mt = 0; mt < 2; ++mt)
            #pragma unroll
            for (int nt = 0; nt < 12; ++nt)
                #pragma unroll
                for (int i = 0; i < 4; ++i) acc[mt][nt][i] = 0.f;

        #pragma unroll
        for (int ks = 0; ks < 6; ++ks) {
            uint abig[2][4], ares[2][4];
            #pragma unroll
            for (int mt = 0; mt < 2; ++mt) {
                int r = wid * 32 + mt * 16 + g;
                float x0 = GsF[r * 52 + ks * 8 + tig];
                float x1 = GsF[(r + 8) * 52 + ks * 8 + tig];
                float x2 = GsF[r * 52 + ks * 8 + tig + 4];
                float x3 = GsF[(r + 8) * 52 + ks * 8 + tig + 4];
                abig[mt][0] = f2tf(x0); ares[mt][0] = f2tf(x0 - __uint_as_float(abig[mt][0]));
                abig[mt][1] = f2tf(x1); ares[mt][1] = f2tf(x1 - __uint_as_float(abig[mt][1]));
                abig[mt][2] = f2tf(x2); ares[mt][2] = f2tf(x2 - __uint_as_float(abig[mt][2]));
                abig[mt][3] = f2tf(x3); ares[mt][3] = f2tf(x3 - __uint_as_float(abig[mt][3]));
            }
            #pragma unroll
            for (int nt = 0; nt < 12; ++nt) {
                uint bb[2], br[2];
                int k0i = (ks * 8 + tig) * 104 + nt * 8 + g;
                int k1i = (ks * 8 + tig + 4) * 104 + nt * 8 + g;
                bb[0] = Wbig[k0i]; bb[1] = Wbig[k1i];
                br[0] = Wres[k0i]; br[1] = Wres[k1i];
                #pragma unroll
                for (int mt = 0; mt < 2; ++mt) {
                    mma_tf32(acc[mt][nt], ares[mt], bb);
                    mma_tf32(acc[mt][nt], abig[mt], br);
                    mma_tf32(acc[mt][nt], abig[mt], bb);
                }
            }
        }

        // epilogue: relu(acc + tjb) . ws2, reduce over the 4 tig lanes
        #pragma unroll
        for (int mt = 0; mt < 2; ++mt) {
            float s0 = 0.f, s1 = 0.f;
            #pragma unroll
            for (int nt = 0; nt < 12; ++nt) {
                int m = nt * 8 + 2 * tig;
                float t0 = tjb_s[m], t1 = tjb_s[m + 1];
                float w0 = ws2_s[m], w1 = ws2_s[m + 1];
                s0 = fmaf(fmaxf(acc[mt][nt][0] + t0, 0.f), w0, s0);
                s0 = fmaf(fmaxf(acc[mt][nt][1] + t1, 0.f), w1, s0);
                s1 = fmaf(fmaxf(acc[mt][nt][2] + t0, 0.f), w0, s1);
                s1 = fmaf(fmaxf(acc[mt][nt][3] + t1, 0.f), w1, s1);
            }
            s0 += __shfl_xor_sync(0xffffffffu, s0, 1);
            s0 += __shfl_xor_sync(0xffffffffu, s0, 2);
            s1 += __shfl_xor_sync(0xffffffffu, s1, 1);
            s1 += __shfl_xor_sync(0xffffffffu, s1, 2);
            if (tig == 0) {
                int q = q0 + wid * 32 + mt * 16 + g;
                logits_s[q] = s0;
                logits_s[q + 8] = s1;
            }
        }
        __syncthreads();
    }

    // mask + bs2
    const float bs2v = *bs2;
    #pragma unroll
    for (int q = tid; q < 512; q += 128) {
        float mv = (float)attn_mask[b * 512 + q];
        logits_s[q] += bs2v + (1.f - mv) * (-3.402823466e38f);
    }
    __syncthreads();

    // softmax over 512
    float lmax = -INFINITY;
    #pragma unroll
    for (int q = tid; q < 512; q += 128) lmax = fmaxf(lmax, logits_s[q]);
    #pragma unroll
    for (int o = 16; o > 0; o >>= 1) lmax = fmaxf(lmax, __shfl_xor_sync(0xffffffffu, lmax, o));
    if (lane == 0) red_s[wid] = lmax;
    __syncthreads();
    lmax = fmaxf(fmaxf(red_s[0], red_s[1]), fmaxf(red_s[2], red_s[3]));

    float lsum = 0.f;
    float ev[4];
    #pragma unroll
    for (int u = 0; u < 4; ++u) {
        int q = tid + u * 128;
        ev[u] = expf(logits_s[q] - lmax);
        lsum += ev[u];
    }
    #pragma unroll
    for (int o = 16; o > 0; o >>= 1) lsum += __shfl_xor_sync(0xffffffffu, lsum, o);
    if (lane == 0) red_s[4 + wid] = lsum;
    __syncthreads();
    const float inv = 1.f / (red_s[4] + red_s[5] + red_s[6] + red_s[7]);
    #pragma unroll
    for (int u = 0; u < 4; ++u) {
        int q = tid + u * 128;
        probs[(long)pg * 512 + q] = ev[u] * inv;
    }
}

// ---------------- launch ----------------
extern "C" void kernel_launch(void* const* d_in, const int* in_sizes, int n_in,
                              void* d_out, int out_size)
{
    const float* Hj   = (const float*)d_in[0];
    const float* Hi   = (const float*)d_in[1];
    const float* Wpj  = (const float*)d_in[2];
    const float* Wpi  = (const float*)d_in[3];
    const float* Ws1  = (const float*)d_in[4];
    const float* bs1  = (const float*)d_in[5];
    const float* ws2  = (const float*)d_in[6];
    const float* bs2  = (const float*)d_in[7];
    const float* Wv1  = (const float*)d_in[8];
    const float* bv1  = (const float*)d_in[9];
    const float* Wv2  = (const float*)d_in[10];
    const float* bv2  = (const float*)d_in[11];
    const float* alpha= (const float*)d_in[12];
    const int*   mask = (const int*)d_in[13];
    float* out = (float*)d_out;

    float *Zj, *Zi, *tjb, *probs, *ctx, *mhid;
    cudaGetSymbolAddress((void**)&Zj, g_Zj);
    cudaGetSymbolAddress((void**)&Zi, g_Zi);
    cudaGetSymbolAddress((void**)&tjb, g_tjb);
    cudaGetSymbolAddress((void**)&probs, g_probs);
    cudaGetSymbolAddress((void**)&ctx, g_ctx);
    cudaGetSymbolAddress((void**)&mhid, g_mhid);

    static int attr_done = 0;
    if (!attr_done) {
        cudaFuncSetAttribute(pairwise_tc3,
                             cudaFuncAttributeMaxDynamicSharedMemorySize, PW6_BYTES);
        attr_done = 1;
    }

    // Zj = H_j @ Wpj ; Zi = H_i @ Wpi   (2048 x 24, K=768), batched
    sgemm_small2<<<dim3(1, ROWS/64, 2), 256>>>(
        Hj, Wpj, Zj, nullptr, Hi, Wpi, Zi, nullptr,
        ROWS, DD, HD, HD, DD, DD);

    // tjb = Zj @ Ws1[0:24] + bs1   (2048 x 96, K=24)
    sgemm_small2<<<dim3(2, ROWS/64, 1), 256>>>(
        Zj, Ws1, tjb, bs1, nullptr, nullptr, nullptr, nullptr,
        ROWS, MMDIM, DD, DD, MMDIM, MMDIM);

    // fused pairwise logits + softmax -> probs (3xTF32 tensor cores)
    pairwise_tc3<<<ROWS, 128, PW6_BYTES>>>(
        Zj, Zi, tjb, Ws1, ws2, bs2, mask, probs);

    // ctx = probs @ H_i   (batched 4x: 512 x 768, K=512) — tf32 tensor cores
    gemm_tc2<0,false,false,false><<<dim3(HD/64, SEQ/64, BATCH), 256>>>(
        probs, Hi, ctx, SEQ, SEQ, HD, HD, nullptr, nullptr,
        (long)SEQ*SEQ, (long)SEQ*HD, (long)SEQ*HD, nullptr, nullptr);

    // mhid = relu([ctx|Hj|ctx*Hj] @ Wv1 + bv1)   (2048 x 768, K=2304; X fused)
    gemm_tc2<1,true,true,false><<<dim3(OO/64, ROWS/64, 1), 256>>>(
        nullptr, Wv1, mhid, XCOLS, 0, OO, OO, bv1, nullptr,
        0, 0, 0, ctx, Hj);

    // out = alpha * (mhid @ Wv2 + bv2)   (2048 x 768, K=768)
    gemm_tc2<0,true,false,true><<<dim3(HD/64, ROWS/64, 1), 256>>>(
        mhid, Wv2, out, OO, OO, HD, HD, bv2, alpha,
        0, 0, 0, nullptr, nullptr);
}

// round 14
// speedup vs baseline: 3.3378x; 1.2279x over previous
#include <cuda_runtime.h>
#include <math.h>

#define BATCH 4
#define SEQ   512
#define HD    768
#define DD    24
#define MMDIM 96
#define OO    768
#define ROWS  (BATCH*SEQ)       // 2048
#define XCOLS (3*HD)            // 2304

typedef unsigned long long ull;
typedef unsigned int uint;

// ---------------- scratch (no allocations allowed) ----------------
__device__ float g_Zj[ROWS*DD];
__device__ float g_Zi[ROWS*DD];
__device__ float g_probs[(long)BATCH*SEQ*SEQ];
__device__ float g_ctx[(long)ROWS*HD];
__device__ float g_mhid[(long)ROWS*OO];

// ---------------- tf32 helpers ----------------
__device__ __forceinline__ uint f2tf(float x) {
    uint r; asm("cvt.rna.tf32.f32 %0, %1;" : "=r"(r) : "f"(x)); return r;
}
__device__ __forceinline__ void mma_tf32(float* c, const uint* a, const uint* b) {
    asm volatile(
        "mma.sync.aligned.m16n8k8.row.col.f32.tf32.tf32.f32 "
        "{%0,%1,%2,%3}, {%4,%5,%6,%7}, {%8,%9}, {%0,%1,%2,%3};"
        : "+f"(c[0]), "+f"(c[1]), "+f"(c[2]), "+f"(c[3])
        : "r"(a[0]), "r"(a[1]), "r"(a[2]), "r"(a[3]), "r"(b[0]), "r"(b[1]));
}

// ---------------- small generic SGEMM, z-batched over pointer pairs ----------------
__global__ __launch_bounds__(256)
void sgemm_small2(const float* __restrict__ A0, const float* __restrict__ B0,
                  float* __restrict__ C0, const float* __restrict__ bias0,
                  const float* __restrict__ A1, const float* __restrict__ B1,
                  float* __restrict__ C1, const float* __restrict__ bias1,
                  int M, int N, int K, int lda, int ldb, int ldc)
{
    __shared__ float As[16][64];
    __shared__ float Bs[16][64];
    const float* A = blockIdx.z ? A1 : A0;
    const float* B = blockIdx.z ? B1 : B0;
    float*       C = blockIdx.z ? C1 : C0;
    const float* bias = blockIdx.z ? bias1 : bias0;

    const int tid = threadIdx.x;
    const int tx = tid & 15, ty = tid >> 4;
    const int row0 = blockIdx.y * 64;
    const int col0 = blockIdx.x * 64;

    float acc[4][4] = {};
    for (int k0 = 0; k0 < K; k0 += 16) {
        #pragma unroll
        for (int u = 0; u < 4; ++u) {
            int t = tid + u * 256;
            int r = t >> 4, kk = t & 15;
            int gr = row0 + r, gk = k0 + kk;
            float v = 0.f;
            if (gr < M && gk < K) v = A[(long)gr * lda + gk];
            As[kk][r] = v;
        }
        #pragma unroll
        for (int u = 0; u < 4; ++u) {
            int t = tid + u * 256;
            int kk = t >> 6, n = t & 63;
            int gk = k0 + kk, gn = col0 + n;
            float v = 0.f;
            if (gk < K && gn < N) v = B[(long)gk * ldb + gn];
            Bs[kk][n] = v;
        }
        __syncthreads();
        #pragma unroll
        for (int kk = 0; kk < 16; ++kk) {
            float4 a4 = *(const float4*)&As[kk][ty * 4];
            float4 b4 = *(const float4*)&Bs[kk][tx * 4];
            float a[4] = {a4.x, a4.y, a4.z, a4.w};
            float b[4] = {b4.x, b4.y, b4.z, b4.w};
            #pragma unroll
            for (int i = 0; i < 4; ++i)
                #pragma unroll
                for (int j = 0; j < 4; ++j)
                    acc[i][j] = fmaf(a[i], b[j], acc[i][j]);
        }
        __syncthreads();
    }
    #pragma unroll
    for (int i = 0; i < 4; ++i) {
        int r = row0 + ty * 4 + i;
        if (r >= M) continue;
        #pragma unroll
        for (int j = 0; j < 4; ++j) {
            int c = col0 + tx * 4 + j;
            if (c >= N) continue;
            float v = acc[i][j];
            if (bias) v += bias[c];
            C[(long)r * ldc + c] = v;
        }
    }
}

// ---------------- gemm_tc2 (R11, frozen): 64x64 tile, 256 threads, tf32 mma ----------------
template<int AMODE, bool BIAS, bool RELU, bool SCALE>
__global__ __launch_bounds__(256)
void gemm_tc2(const float* __restrict__ A, const float* __restrict__ B,
              float* __restrict__ C, int K, int lda, int ldb, int ldc,
              const float* __restrict__ bias, const float* __restrict__ alpha_ptr,
              long sA, long sB, long sC,
              const float* __restrict__ Actx, const float* __restrict__ Ahj)
{
    __shared__ uint As[2][64][36];
    __shared__ uint Bs[2][32][72];

    const int bz = blockIdx.z;
    if (AMODE == 0) A += (long)bz * sA;
    B += (long)bz * sB;  C += (long)bz * sC;

    const int tid = threadIdx.x;
    const int wid = tid >> 5, lane = tid & 31;
    const int wm = wid & 3, wn = wid >> 2;
    const int g = lane >> 2, tig = lane & 3;
    const int row0 = blockIdx.y * 64;
    const int col0 = blockIdx.x * 64;

    const int ar = tid >> 3, akc = tid & 7;
    const int bk = tid >> 4, bn4 = tid & 15;

    float acc[4][4];
    #pragma unroll
    for (int nt = 0; nt < 4; ++nt)
        #pragma unroll
        for (int i = 0; i < 4; ++i) acc[nt][i] = 0.f;

    uint4 pa[2], pb[2];

    auto loadA = [&](int kt) {
        #pragma unroll
        for (int u = 0; u < 2; ++u) {
            int r = ar + u * 32;
            int gk = kt + akc * 4;
            float4 v;
            if (AMODE == 0) {
                v = *(const float4*)&A[(long)(row0 + r) * lda + gk];
            } else {
                long ridx = (long)(row0 + r) * HD;
                if (gk < HD) {
                    v = *(const float4*)&Actx[ridx + gk];
                } else if (gk < 2 * HD) {
                    v = *(const float4*)&Ahj[ridx + gk - HD];
                } else {
                    float4 c4 = *(const float4*)&Actx[ridx + gk - 2 * HD];
                    float4 h4 = *(const float4*)&Ahj[ridx + gk - 2 * HD];
                    v.x = c4.x * h4.x; v.y = c4.y * h4.y;
                    v.z = c4.z * h4.z; v.w = c4.w * h4.w;
                }
            }
            pa[u].x = f2tf(v.x); pa[u].y = f2tf(v.y);
            pa[u].z = f2tf(v.z); pa[u].w = f2tf(v.w);
        }
    };
    auto loadB = [&](int kt) {
        #pragma unroll
        for (int u = 0; u < 2; ++u) {
            int k = bk + u * 16;
            float4 v = *(const float4*)&B[(long)(kt + k) * ldb + col0 + bn4 * 4];
            pb[u].x = f2tf(v.x); pb[u].y = f2tf(v.y);
            pb[u].z = f2tf(v.z); pb[u].w = f2tf(v.w);
        }
    };
    auto storeT = [&](int buf) {
        #pragma unroll
        for (int u = 0; u < 2; ++u) {
            *(uint4*)&As[buf][ar + u * 32][akc * 4] = pa[u];
            *(uint4*)&Bs[buf][bk + u * 16][bn4 * 4] = pb[u];
        }
    };

    loadA(0); loadB(0);
    storeT(0);
    __syncthreads();

    int cur = 0;
    for (int kt = 0; kt < K; kt += 32) {
        const bool more = (kt + 32) < K;
        if (more) { loadA(kt + 32); loadB(kt + 32); }

        #pragma unroll
        for (int ks = 0; ks < 4; ++ks) {
            uint a[4], b[4][2];
            int r = wm * 16 + g;
            a[0] = As[cur][r][ks * 8 + tig];
            a[1] = As[cur][r + 8][ks * 8 + tig];
            a[2] = As[cur][r][ks * 8 + tig + 4];
            a[3] = As[cur][r + 8][ks * 8 + tig + 4];
            #pragma unroll
            for (int nt = 0; nt < 4; ++nt) {
                int n = wn * 32 + nt * 8 + g;
                b[nt][0] = Bs[cur][ks * 8 + tig][n];
                b[nt][1] = Bs[cur][ks * 8 + tig + 4][n];
            }
            #pragma unroll
            for (int nt = 0; nt < 4; ++nt)
                mma_tf32(acc[nt], a, b[nt]);
        }

        if (more) storeT(cur ^ 1);
        __syncthreads();
        if (more) cur ^= 1;
    }

    float alpha = 1.f;
    if (SCALE) alpha = *alpha_ptr;

    int r = row0 + wm * 16 + g;
    #pragma unroll
    for (int nt = 0; nt < 4; ++nt) {
        int c = col0 + wn * 32 + nt * 8 + 2 * tig;
        float b0 = 0.f, b1 = 0.f;
        if (BIAS) { b0 = bias[c]; b1 = bias[c + 1]; }
        float v0 = acc[nt][0] + b0;
        float v1 = acc[nt][1] + b1;
        float v2 = acc[nt][2] + b0;
        float v3 = acc[nt][3] + b1;
        if (RELU) {
            v0 = fmaxf(v0, 0.f); v1 = fmaxf(v1, 0.f);
            v2 = fmaxf(v2, 0.f); v3 = fmaxf(v3, 0.f);
        }
        v0 *= alpha; v1 *= alpha; v2 *= alpha; v3 *= alpha;
        *(float2*)&C[(long)r * ldc + c] = make_float2(v0, v1);
        *(float2*)&C[(long)(r + 8) * ldc + c] = make_float2(v2, v3);
    }
}

// ---------------- pairwise v7: single-pass tf32, tjb fused in-block ----------------
// One block per p (128 thr, 4 warps). B = folded weights [W'|W1d] tf32 in smem
// (stride 104, conflict-free). G per q-tile of 128 stored as tf32 (stride 52).
// tjb computed in-block: tjb[m] = bs1[m] + Zj[p] . W1j[:,m].
#define PW7_W_OFF    0                        // W tf32 [48][104]
#define PW7_G_OFF    (48*104)                 // G tf32 [128][52]
#define PW7_LOG_OFF  (PW7_G_OFF + 128*52)     // 512 float
#define PW7_TJB_OFF  (PW7_LOG_OFF + 512)
#define PW7_WS2_OFF  (PW7_TJB_OFF + 96)
#define PW7_ZJP_OFF  (PW7_WS2_OFF + 96)
#define PW7_RED_OFF  (PW7_ZJP_OFF + 24)
#define PW7_WORDS    (PW7_RED_OFF + 8)
#define PW7_BYTES    (PW7_WORDS * 4)          // ~49.5 KB

__global__ __launch_bounds__(128)
void pairwise_tc1(const float* __restrict__ Zj, const float* __restrict__ Zi,
                  const float* __restrict__ Ws1, const float* __restrict__ bs1,
                  const float* __restrict__ ws2,
                  const float* __restrict__ bs2, const int* __restrict__ attn_mask,
                  float* __restrict__ probs)
{
    extern __shared__ uint dynU[];
    uint*  Wtc      = dynU + PW7_W_OFF;
    uint*  Gs       = dynU + PW7_G_OFF;
    float* logits_s = (float*)(dynU + PW7_LOG_OFF);
    float* tjb_s    = (float*)(dynU + PW7_TJB_OFF);
    float* ws2_s    = (float*)(dynU + PW7_WS2_OFF);
    float* Zjp_s    = (float*)(dynU + PW7_ZJP_OFF);
    float* red_s    = (float*)(dynU + PW7_RED_OFF);

    const int tid = threadIdx.x;
    const int wid = tid >> 5, lane = tid & 31;
    const int g = lane >> 2, tig = lane & 3;
    const int pg = blockIdx.x;
    const int b = pg >> 9;

    if (tid < 24) Zjp_s[tid] = Zj[pg * 24 + tid];
    if (tid < 96) ws2_s[tid] = ws2[tid];
    __syncthreads();

    // tjb[m] = bs1[m] + sum_d Zjp[d] * W1j[d][m]   (Ws1 rows 0..23)
    if (tid < 96) {
        float s = bs1[tid];
        #pragma unroll
        for (int d = 0; d < 24; ++d)
            s = fmaf(Zjp_s[d], Ws1[d * 96 + tid], s);
        tjb_s[tid] = s;
    }

    // Folded weights (tf32): rows 0..23 = W1i + zjp*W1h, rows 24..47 = W1d.
    for (int idx = tid; idx < 24 * 96; idx += 128) {
        int d = idx / 96, m = idx - d * 96;
        float wp = fmaf(Zjp_s[d], Ws1[(48 + d) * 96 + m], Ws1[(24 + d) * 96 + m]);
        Wtc[d * 104 + m]        = f2tf(wp);
        Wtc[(24 + d) * 104 + m] = f2tf(Ws1[(72 + d) * 96 + m]);
    }
    __syncthreads();

    #pragma unroll 1
    for (int qt = 0; qt < 4; ++qt) {
        const int q0 = qt * 128;

        // Build G tile (tf32): one thread per q row, uint4 stores (conflict-free).
        {
            const int q = tid;
            const float* zrow = &Zi[((long)(b * 512 + q0 + q)) * 24];
            float4 z4[6];
            #pragma unroll
            for (int u = 0; u < 6; ++u) z4[u] = *(const float4*)&zrow[u * 4];
            uint* dst = &Gs[q * 52];
            #pragma unroll
            for (int u = 0; u < 6; ++u) {
                uint4 o;
                o.x = f2tf(z4[u].x); o.y = f2tf(z4[u].y);
                o.z = f2tf(z4[u].z); o.w = f2tf(z4[u].w);
                *(uint4*)&dst[u * 4] = o;
            }
            #pragma unroll
            for (int u = 0; u < 6; ++u) {
                uint4 o;
                o.x = f2tf(fabsf(Zjp_s[u*4+0] - z4[u].x));
                o.y = f2tf(fabsf(Zjp_s[u*4+1] - z4[u].y));
                o.z = f2tf(fabsf(Zjp_s[u*4+2] - z4[u].z));
                o.w = f2tf(fabsf(Zjp_s[u*4+3] - z4[u].w));
                *(uint4*)&dst[24 + u * 4] = o;
            }
        }
        __syncthreads();

        float acc[2][12][4];
        #pragma unroll
        for (int mt = 0; mt < 2; ++mt)
            #pragma unroll
            for (int nt = 0; nt < 12; ++nt)
                #pragma unroll
                for (int i = 0; i < 4; ++i) acc[mt][nt][i] = 0.f;

        #pragma unroll
        for (int ks = 0; ks < 6; ++ks) {
            uint a[2][4];
            #pragma unroll
            for (int mt = 0; mt < 2; ++mt) {
                int r = wid * 32 + mt * 16 + g;
                a[mt][0] = Gs[r * 52 + ks * 8 + tig];
                a[mt][1] = Gs[(r + 8) * 52 + ks * 8 + tig];
                a[mt][2] = Gs[r * 52 + ks * 8 + tig + 4];
                a[mt][3] = Gs[(r + 8) * 52 + ks * 8 + tig + 4];
            }
            #pragma unroll
            for (int nt = 0; nt < 12; ++nt) {
                uint bb[2];
                bb[0] = Wtc[(ks * 8 + tig) * 104 + nt * 8 + g];
                bb[1] = Wtc[(ks * 8 + tig + 4) * 104 + nt * 8 + g];
                mma_tf32(acc[0][nt], a[0], bb);
                mma_tf32(acc[1][nt], a[1], bb);
            }
        }

        // epilogue: relu(acc + tjb) . ws2, reduce over the 4 tig lanes
        #pragma unroll
        for (int mt = 0; mt < 2; ++mt) {
            float s0 = 0.f, s1 = 0.f;
            #pragma unroll
            for (int nt = 0; nt < 12; ++nt) {
                int m = nt * 8 + 2 * tig;
                float t0 = tjb_s[m], t1 = tjb_s[m + 1];
                float w0 = ws2_s[m], w1 = ws2_s[m + 1];
                s0 = fmaf(fmaxf(acc[mt][nt][0] + t0, 0.f), w0, s0);
                s0 = fmaf(fmaxf(acc[mt][nt][1] + t1, 0.f), w1, s0);
                s1 = fmaf(fmaxf(acc[mt][nt][2] + t0, 0.f), w0, s1);
                s1 = fmaf(fmaxf(acc[mt][nt][3] + t1, 0.f), w1, s1);
            }
            s0 += __shfl_xor_sync(0xffffffffu, s0, 1);
            s0 += __shfl_xor_sync(0xffffffffu, s0, 2);
            s1 += __shfl_xor_sync(0xffffffffu, s1, 1);
            s1 += __shfl_xor_sync(0xffffffffu, s1, 2);
            if (tig == 0) {
                int q = q0 + wid * 32 + mt * 16 + g;
                logits_s[q] = s0;
                logits_s[q + 8] = s1;
            }
        }
        __syncthreads();
    }

    // mask + bs2
    const float bs2v = *bs2;
    #pragma unroll
    for (int q = tid; q < 512; q += 128) {
        float mv = (float)attn_mask[b * 512 + q];
        logits_s[q] += bs2v + (1.f - mv) * (-3.402823466e38f);
    }
    __syncthreads();

    // softmax over 512
    float lmax = -INFINITY;
    #pragma unroll
    for (int q = tid; q < 512; q += 128) lmax = fmaxf(lmax, logits_s[q]);
    #pragma unroll
    for (int o = 16; o > 0; o >>= 1) lmax = fmaxf(lmax, __shfl_xor_sync(0xffffffffu, lmax, o));
    if (lane == 0) red_s[wid] = lmax;
    __syncthreads();
    lmax = fmaxf(fmaxf(red_s[0], red_s[1]), fmaxf(red_s[2], red_s[3]));

    float lsum = 0.f;
    float ev[4];
    #pragma unroll
    for (int u = 0; u < 4; ++u) {
        int q = tid + u * 128;
        ev[u] = expf(logits_s[q] - lmax);
        lsum += ev[u];
    }
    #pragma unroll
    for (int o = 16; o > 0; o >>= 1) lsum += __shfl_xor_sync(0xffffffffu, lsum, o);
    if (lane == 0) red_s[4 + wid] = lsum;
    __syncthreads();
    const float inv = 1.f / (red_s[4] + red_s[5] + red_s[6] + red_s[7]);
    #pragma unroll
    for (int u = 0; u < 4; ++u) {
        int q = tid + u * 128;
        probs[(long)pg * 512 + q] = ev[u] * inv;
    }
}

// ---------------- launch ----------------
extern "C" void kernel_launch(void* const* d_in, const int* in_sizes, int n_in,
                              void* d_out, int out_size)
{
    const float* Hj   = (const float*)d_in[0];
    const float* Hi   = (const float*)d_in[1];
    const float* Wpj  = (const float*)d_in[2];
    const float* Wpi  = (const float*)d_in[3];
    const float* Ws1  = (const float*)d_in[4];
    const float* bs1  = (const float*)d_in[5];
    const float* ws2  = (const float*)d_in[6];
    const float* bs2  = (const float*)d_in[7];
    const float* Wv1  = (const float*)d_in[8];
    const float* bv1  = (const float*)d_in[9];
    const float* Wv2  = (const float*)d_in[10];
    const float* bv2  = (const float*)d_in[11];
    const float* alpha= (const float*)d_in[12];
    const int*   mask = (const int*)d_in[13];
    float* out = (float*)d_out;

    float *Zj, *Zi, *probs, *ctx, *mhid;
    cudaGetSymbolAddress((void**)&Zj, g_Zj);
    cudaGetSymbolAddress((void**)&Zi, g_Zi);
    cudaGetSymbolAddress((void**)&probs, g_probs);
    cudaGetSymbolAddress((void**)&ctx, g_ctx);
    cudaGetSymbolAddress((void**)&mhid, g_mhid);

    static int attr_done = 0;
    if (!attr_done) {
        cudaFuncSetAttribute(pairwise_tc1,
                             cudaFuncAttributeMaxDynamicSharedMemorySize, PW7_BYTES);
        attr_done = 1;
    }

    // Zj = H_j @ Wpj ; Zi = H_i @ Wpi   (2048 x 24, K=768), batched
    sgemm_small2<<<dim3(1, ROWS/64, 2), 256>>>(
        Hj, Wpj, Zj, nullptr, Hi, Wpi, Zi, nullptr,
        ROWS, DD, HD, HD, DD, DD);

    // fused pairwise (tjb computed in-block) + softmax -> probs
    pairwise_tc1<<<ROWS, 128, PW7_BYTES>>>(
        Zj, Zi, Ws1, bs1, ws2, bs2, mask, probs);

    // ctx = probs @ H_i   (batched 4x: 512 x 768, K=512) — tf32 tensor cores
    gemm_tc2<0,false,false,false><<<dim3(HD/64, SEQ/64, BATCH), 256>>>(
        probs, Hi, ctx, SEQ, SEQ, HD, HD, nullptr, nullptr,
        (long)SEQ*SEQ, (long)SEQ*HD, (long)SEQ*HD, nullptr, nullptr);

    // mhid = relu([ctx|Hj|ctx*Hj] @ Wv1 + bv1)   (2048 x 768, K=2304; X fused)
    gemm_tc2<1,true,true,false><<<dim3(OO/64, ROWS/64, 1), 256>>>(
        nullptr, Wv1, mhid, XCOLS, 0, OO, OO, bv1, nullptr,
        0, 0, 0, ctx, Hj);

    // out = alpha * (mhid @ Wv2 + bv2)   (2048 x 768, K=768)
    gemm_tc2<0,true,false,true><<<dim3(HD/64, ROWS/64, 1), 256>>>(
        mhid, Wv2, out, OO, OO, HD, HD, bv2, alpha,
        0, 0, 0, nullptr, nullptr);
}

// round 16
// speedup vs baseline: 3.4714x; 1.0400x over previous
#include <cuda_runtime.h>
#include <math.h>

#define BATCH 4
#define SEQ   512
#define HD    768
#define DD    24
#define MMDIM 96
#define OO    768
#define ROWS  (BATCH*SEQ)       // 2048
#define XCOLS (3*HD)            // 2304

typedef unsigned long long ull;
typedef unsigned int uint;

// ---------------- scratch (no allocations allowed) ----------------
__device__ float g_Zj[ROWS*DD];
__device__ float g_Zi[ROWS*DD];
__device__ float g_probs[(long)BATCH*SEQ*SEQ];
__device__ float g_ctx[(long)ROWS*HD];
__device__ float g_mhid[(long)ROWS*OO];

// ---------------- tf32 helpers ----------------
__device__ __forceinline__ uint f2tf(float x) {
    uint r; asm("cvt.rna.tf32.f32 %0, %1;" : "=r"(r) : "f"(x)); return r;
}
__device__ __forceinline__ void mma_tf32(float* c, const uint* a, const uint* b) {
    asm volatile(
        "mma.sync.aligned.m16n8k8.row.col.f32.tf32.tf32.f32 "
        "{%0,%1,%2,%3}, {%4,%5,%6,%7}, {%8,%9}, {%0,%1,%2,%3};"
        : "+f"(c[0]), "+f"(c[1]), "+f"(c[2]), "+f"(c[3])
        : "r"(a[0]), "r"(a[1]), "r"(a[2]), "r"(a[3]), "r"(b[0]), "r"(b[1]));
}

// ---------------- small generic SGEMM, z-batched over pointer pairs ----------------
__global__ __launch_bounds__(256)
void sgemm_small2(const float* __restrict__ A0, const float* __restrict__ B0,
                  float* __restrict__ C0, const float* __restrict__ bias0,
                  const float* __restrict__ A1, const float* __restrict__ B1,
                  float* __restrict__ C1, const float* __restrict__ bias1,
                  int M, int N, int K, int lda, int ldb, int ldc)
{
    __shared__ float As[16][64];
    __shared__ float Bs[16][64];
    const float* A = blockIdx.z ? A1 : A0;
    const float* B = blockIdx.z ? B1 : B0;
    float*       C = blockIdx.z ? C1 : C0;
    const float* bias = blockIdx.z ? bias1 : bias0;

    const int tid = threadIdx.x;
    const int tx = tid & 15, ty = tid >> 4;
    const int row0 = blockIdx.y * 64;
    const int col0 = blockIdx.x * 64;

    float acc[4][4] = {};
    for (int k0 = 0; k0 < K; k0 += 16) {
        #pragma unroll
        for (int u = 0; u < 4; ++u) {
            int t = tid + u * 256;
            int r = t >> 4, kk = t & 15;
            int gr = row0 + r, gk = k0 + kk;
            float v = 0.f;
            if (gr < M && gk < K) v = A[(long)gr * lda + gk];
            As[kk][r] = v;
        }
        #pragma unroll
        for (int u = 0; u < 4; ++u) {
            int t = tid + u * 256;
            int kk = t >> 6, n = t & 63;
            int gk = k0 + kk, gn = col0 + n;
            float v = 0.f;
            if (gk < K && gn < N) v = B[(long)gk * ldb + gn];
            Bs[kk][n] = v;
        }
        __syncthreads();
        #pragma unroll
        for (int kk = 0; kk < 16; ++kk) {
            float4 a4 = *(const float4*)&As[kk][ty * 4];
            float4 b4 = *(const float4*)&Bs[kk][tx * 4];
            float a[4] = {a4.x, a4.y, a4.z, a4.w};
            float b[4] = {b4.x, b4.y, b4.z, b4.w};
            #pragma unroll
            for (int i = 0; i < 4; ++i)
                #pragma unroll
                for (int j = 0; j < 4; ++j)
                    acc[i][j] = fmaf(a[i], b[j], acc[i][j]);
        }
        __syncthreads();
    }
    #pragma unroll
    for (int i = 0; i < 4; ++i) {
        int r = row0 + ty * 4 + i;
        if (r >= M) continue;
        #pragma unroll
        for (int j = 0; j < 4; ++j) {
            int c = col0 + tx * 4 + j;
            if (c >= N) continue;
            float v = acc[i][j];
            if (bias) v += bias[c];
            C[(long)r * ldc + c] = v;
        }
    }
}

// ---------------- gemm_tc4: 64x64 tile, 256 threads, split-K x2, tf32 mma ----------------
// 8 warps = 2 k-groups x 4 warps; warp tile 32x32 (2 m-frags x 4 n-frags).
// Per 8-k slice: 16 LDS.32 per 8 mma (2:1 feed). Cross-kg reduction via smem reuse.
// K % 32 == 0, exact-multiple dims, unguarded.
// AMODE 0: plain A. AMODE 1: A = [ctx | Hj | ctx*Hj] generated on the fly.
template<int AMODE, bool BIAS, bool RELU, bool SCALE>
__global__ __launch_bounds__(256)
void gemm_tc4(const float* __restrict__ A, const float* __restrict__ B,
              float* __restrict__ C, int K, int lda, int ldb, int ldc,
              const float* __restrict__ bias, const float* __restrict__ alpha_ptr,
              long sA, long sB, long sC,
              const float* __restrict__ Actx, const float* __restrict__ Ahj)
{
    __shared__ uint As[2][64][36];   // 18.4 KB x2 halves? total 36.9 KB
    __shared__ uint Bs[2][32][72];   // 18.4 KB

    const int bz = blockIdx.z;
    if (AMODE == 0) A += (long)bz * sA;
    B += (long)bz * sB;  C += (long)bz * sC;

    const int tid = threadIdx.x;
    const int wid = tid >> 5, lane = tid & 31;
    const int kg = wid >> 2;                    // k-group 0/1
    const int w4 = wid & 3;
    const int wm = w4 & 1, wn = w4 >> 1;        // 2x2 warp grid, warp tile 32x32
    const int g = lane >> 2, tig = lane & 3;
    const int row0 = blockIdx.y * 64;
    const int col0 = blockIdx.x * 64;

    const int ar = tid >> 3, akc = tid & 7;
    const int bk = tid >> 4, bn4 = tid & 15;

    float acc[2][4][4];
    #pragma unroll
    for (int mt = 0; mt < 2; ++mt)
        #pragma unroll
        for (int nt = 0; nt < 4; ++nt)
            #pragma unroll
            for (int i = 0; i < 4; ++i) acc[mt][nt][i] = 0.f;

    uint4 pa[2], pb[2];

    auto loadA = [&](int kt) {
        #pragma unroll
        for (int u = 0; u < 2; ++u) {
            int r = ar + u * 32;
            int gk = kt + akc * 4;
            float4 v;
            if (AMODE == 0) {
                v = *(const float4*)&A[(long)(row0 + r) * lda + gk];
            } else {
                long ridx = (long)(row0 + r) * HD;
                if (gk < HD) {
                    v = *(const float4*)&Actx[ridx + gk];
                } else if (gk < 2 * HD) {
                    v = *(const float4*)&Ahj[ridx + gk - HD];
                } else {
                    float4 c4 = *(const float4*)&Actx[ridx + gk - 2 * HD];
                    float4 h4 = *(const float4*)&Ahj[ridx + gk - 2 * HD];
                    v.x = c4.x * h4.x; v.y = c4.y * h4.y;
                    v.z = c4.z * h4.z; v.w = c4.w * h4.w;
                }
            }
            pa[u].x = f2tf(v.x); pa[u].y = f2tf(v.y);
            pa[u].z = f2tf(v.z); pa[u].w = f2tf(v.w);
        }
    };
    auto loadB = [&](int kt) {
        #pragma unroll
        for (int u = 0; u < 2; ++u) {
            int k = bk + u * 16;
            float4 v = *(const float4*)&B[(long)(kt + k) * ldb + col0 + bn4 * 4];
            pb[u].x = f2tf(v.x); pb[u].y = f2tf(v.y);
            pb[u].z = f2tf(v.z); pb[u].w = f2tf(v.w);
        }
    };
    auto storeT = [&](int buf) {
        #pragma unroll
        for (int u = 0; u < 2; ++u) {
            *(uint4*)&As[buf][ar + u * 32][akc * 4] = pa[u];
            *(uint4*)&Bs[buf][bk + u * 16][bn4 * 4] = pb[u];
        }
    };

    loadA(0); loadB(0);
    storeT(0);
    __syncthreads();

    int cur = 0;
    for (int kt = 0; kt < K; kt += 32) {
        const bool more = (kt + 32) < K;
        if (more) { loadA(kt + 32); loadB(kt + 32); }

        #pragma unroll
        for (int ks = 0; ks < 2; ++ks) {
            const int kb = kg * 16 + ks * 8;
            uint a[2][4], b[4][2];
            #pragma unroll
            for (int mt = 0; mt < 2; ++mt) {
                int r = wm * 32 + mt * 16 + g;
                a[mt][0] = As[cur][r][kb + tig];
                a[mt][1] = As[cur][r + 8][kb + tig];
                a[mt][2] = As[cur][r][kb + tig + 4];
                a[mt][3] = As[cur][r + 8][kb + tig + 4];
            }
            #pragma unroll
            for (int nt = 0; nt < 4; ++nt) {
                int n = wn * 32 + nt * 8 + g;
                b[nt][0] = Bs[cur][kb + tig][n];
                b[nt][1] = Bs[cur][kb + tig + 4][n];
            }
            #pragma unroll
            for (int nt = 0; nt < 4; ++nt) {
                mma_tf32(acc[0][nt], a[0], b[nt]);
                mma_tf32(acc[1][nt], a[1], b[nt]);
            }
        }

        if (more) storeT(cur ^ 1);
        __syncthreads();
        if (more) cur ^= 1;
    }

    // ---- cross-kg reduction (reuse As: 128 thr x 32 floats = 16 KB < 18.4 KB) ----
    float* red = (float*)&As[0][0][0];
    const int lt = tid & 127;
    if (kg == 1) {
        #pragma unroll
        for (int mt = 0; mt < 2; ++mt)
            #pragma unroll
            for (int nt = 0; nt < 4; ++nt)
                #pragma unroll
                for (int i = 0; i < 4; ++i)
                    red[((mt * 4 + nt) * 4 + i) * 128 + lt] = acc[mt][nt][i];
    }
    __syncthreads();
    if (kg != 0) return;
    #pragma unroll
    for (int mt = 0; mt < 2; ++mt)
        #pragma unroll
        for (int nt = 0; nt < 4; ++nt)
            #pragma unroll
            for (int i = 0; i < 4; ++i)
                acc[mt][nt][i] += red[((mt * 4 + nt) * 4 + i) * 128 + lt];

    float alpha = 1.f;
    if (SCALE) alpha = *alpha_ptr;

    #pragma unroll
    for (int mt = 0; mt < 2; ++mt) {
        int r = row0 + wm * 32 + mt * 16 + g;
        #pragma unroll
        for (int nt = 0; nt < 4; ++nt) {
            int c = col0 + wn * 32 + nt * 8 + 2 * tig;
            float b0 = 0.f, b1 = 0.f;
            if (BIAS) { b0 = bias[c]; b1 = bias[c + 1]; }
            float v0 = acc[mt][nt][0] + b0;
            float v1 = acc[mt][nt][1] + b1;
            float v2 = acc[mt][nt][2] + b0;
            float v3 = acc[mt][nt][3] + b1;
            if (RELU) {
                v0 = fmaxf(v0, 0.f); v1 = fmaxf(v1, 0.f);
                v2 = fmaxf(v2, 0.f); v3 = fmaxf(v3, 0.f);
            }
            v0 *= alpha; v1 *= alpha; v2 *= alpha; v3 *= alpha;
            *(float2*)&C[(long)r * ldc + c] = make_float2(v0, v1);
            *(float2*)&C[(long)(r + 8) * ldc + c] = make_float2(v2, v3);
        }
    }
}

// ---------------- pairwise v7 (R14, frozen): single-pass tf32, tjb fused ----------------
#define PW7_W_OFF    0                        // W tf32 [48][104]
#define PW7_G_OFF    (48*104)                 // G tf32 [128][52]
#define PW7_LOG_OFF  (PW7_G_OFF + 128*52)     // 512 float
#define PW7_TJB_OFF  (PW7_LOG_OFF + 512)
#define PW7_WS2_OFF  (PW7_TJB_OFF + 96)
#define PW7_ZJP_OFF  (PW7_WS2_OFF + 96)
#define PW7_RED_OFF  (PW7_ZJP_OFF + 24)
#define PW7_WORDS    (PW7_RED_OFF + 8)
#define PW7_BYTES    (PW7_WORDS * 4)          // ~49.5 KB

__global__ __launch_bounds__(128)
void pairwise_tc1(const float* __restrict__ Zj, const float* __restrict__ Zi,
                  const float* __restrict__ Ws1, const float* __restrict__ bs1,
                  const float* __restrict__ ws2,
                  const float* __restrict__ bs2, const int* __restrict__ attn_mask,
                  float* __restrict__ probs)
{
    extern __shared__ uint dynU[];
    uint*  Wtc      = dynU + PW7_W_OFF;
    uint*  Gs       = dynU + PW7_G_OFF;
    float* logits_s = (float*)(dynU + PW7_LOG_OFF);
    float* tjb_s    = (float*)(dynU + PW7_TJB_OFF);
    float* ws2_s    = (float*)(dynU + PW7_WS2_OFF);
    float* Zjp_s    = (float*)(dynU + PW7_ZJP_OFF);
    float* red_s    = (float*)(dynU + PW7_RED_OFF);

    const int tid = threadIdx.x;
    const int wid = tid >> 5, lane = tid & 31;
    const int g = lane >> 2, tig = lane & 3;
    const int pg = blockIdx.x;
    const int b = pg >> 9;

    if (tid < 24) Zjp_s[tid] = Zj[pg * 24 + tid];
    if (tid < 96) ws2_s[tid] = ws2[tid];
    __syncthreads();

    if (tid < 96) {
        float s = bs1[tid];
        #pragma unroll
        for (int d = 0; d < 24; ++d)
            s = fmaf(Zjp_s[d], Ws1[d * 96 + tid], s);
        tjb_s[tid] = s;
    }

    for (int idx = tid; idx < 24 * 96; idx += 128) {
        int d = idx / 96, m = idx - d * 96;
        float wp = fmaf(Zjp_s[d], Ws1[(48 + d) * 96 + m], Ws1[(24 + d) * 96 + m]);
        Wtc[d * 104 + m]        = f2tf(wp);
        Wtc[(24 + d) * 104 + m] = f2tf(Ws1[(72 + d) * 96 + m]);
    }
    __syncthreads();

    #pragma unroll 1
    for (int qt = 0; qt < 4; ++qt) {
        const int q0 = qt * 128;

        {
            const int q = tid;
            const float* zrow = &Zi[((long)(b * 512 + q0 + q)) * 24];
            float4 z4[6];
            #pragma unroll
            for (int u = 0; u < 6; ++u) z4[u] = *(const float4*)&zrow[u * 4];
            uint* dst = &Gs[q * 52];
            #pragma unroll
            for (int u = 0; u < 6; ++u) {
                uint4 o;
                o.x = f2tf(z4[u].x); o.y = f2tf(z4[u].y);
                o.z = f2tf(z4[u].z); o.w = f2tf(z4[u].w);
                *(uint4*)&dst[u * 4] = o;
            }
            #pragma unroll
            for (int u = 0; u < 6; ++u) {
                uint4 o;
                o.x = f2tf(fabsf(Zjp_s[u*4+0] - z4[u].x));
                o.y = f2tf(fabsf(Zjp_s[u*4+1] - z4[u].y));
                o.z = f2tf(fabsf(Zjp_s[u*4+2] - z4[u].z));
                o.w = f2tf(fabsf(Zjp_s[u*4+3] - z4[u].w));
                *(uint4*)&dst[24 + u * 4] = o;
            }
        }
        __syncthreads();

        float acc[2][12][4];
        #pragma unroll
        for (int mt = 0; mt < 2; ++mt)
            #pragma unroll
            for (int nt = 0; nt < 12; ++nt)
                #pragma unroll
                for (int i = 0; i < 4; ++i) acc[mt][nt][i] = 0.f;

        #pragma unroll
        for (int ks = 0; ks < 6; ++ks) {
            uint a[2][4];
            #pragma unroll
            for (int mt = 0; mt < 2; ++mt) {
                int r = wid * 32 + mt * 16 + g;
                a[mt][0] = Gs[r * 52 + ks * 8 + tig];
                a[mt][1] = Gs[(r + 8) * 52 + ks * 8 + tig];
                a[mt][2] = Gs[r * 52 + ks * 8 + tig + 4];
                a[mt][3] = Gs[(r + 8) * 52 + ks * 8 + tig + 4];
            }
            #pragma unroll
            for (int nt = 0; nt < 12; ++nt) {
                uint bb[2];
                bb[0] = Wtc[(ks * 8 + tig) * 104 + nt * 8 + g];
                bb[1] = Wtc[(ks * 8 + tig + 4) * 104 + nt * 8 + g];
                mma_tf32(acc[0][nt], a[0], bb);
                mma_tf32(acc[1][nt], a[1], bb);
            }
        }

        #pragma unroll
        for (int mt = 0; mt < 2; ++mt) {
            float s0 = 0.f, s1 = 0.f;
            #pragma unroll
            for (int nt = 0; nt < 12; ++nt) {
                int m = nt * 8 + 2 * tig;
                float t0 = tjb_s[m], t1 = tjb_s[m + 1];
                float w0 = ws2_s[m], w1 = ws2_s[m + 1];
                s0 = fmaf(fmaxf(acc[mt][nt][0] + t0, 0.f), w0, s0);
                s0 = fmaf(fmaxf(acc[mt][nt][1] + t1, 0.f), w1, s0);
                s1 = fmaf(fmaxf(acc[mt][nt][2] + t0, 0.f), w0, s1);
                s1 = fmaf(fmaxf(acc[mt][nt][3] + t1, 0.f), w1, s1);
            }
            s0 += __shfl_xor_sync(0xffffffffu, s0, 1);
            s0 += __shfl_xor_sync(0xffffffffu, s0, 2);
            s1 += __shfl_xor_sync(0xffffffffu, s1, 1);
            s1 += __shfl_xor_sync(0xffffffffu, s1, 2);
            if (tig == 0) {
                int q = q0 + wid * 32 + mt * 16 + g;
                logits_s[q] = s0;
                logits_s[q + 8] = s1;
            }
        }
        __syncthreads();
    }

    const float bs2v = *bs2;
    #pragma unroll
    for (int q = tid; q < 512; q += 128) {
        float mv = (float)attn_mask[b * 512 + q];
        logits_s[q] += bs2v + (1.f - mv) * (-3.402823466e38f);
    }
    __syncthreads();

    float lmax = -INFINITY;
    #pragma unroll
    for (int q = tid; q < 512; q += 128) lmax = fmaxf(lmax, logits_s[q]);
    #pragma unroll
    for (int o = 16; o > 0; o >>= 1) lmax = fmaxf(lmax, __shfl_xor_sync(0xffffffffu, lmax, o));
    if (lane == 0) red_s[wid] = lmax;
    __syncthreads();
    lmax = fmaxf(fmaxf(red_s[0], red_s[1]), fmaxf(red_s[2], red_s[3]));

    float lsum = 0.f;
    float ev[4];
    #pragma unroll
    for (int u = 0; u < 4; ++u) {
        int q = tid + u * 128;
        ev[u] = expf(logits_s[q] - lmax);
        lsum += ev[u];
    }
    #pragma unroll
    for (int o = 16; o > 0; o >>= 1) lsum += __shfl_xor_sync(0xffffffffu, lsum, o);
    if (lane == 0) red_s[4 + wid] = lsum;
    __syncthreads();
    const float inv = 1.f / (red_s[4] + red_s[5] + red_s[6] + red_s[7]);
    #pragma unroll
    for (int u = 0; u < 4; ++u) {
        int q = tid + u * 128;
        probs[(long)pg * 512 + q] = ev[u] * inv;
    }
}

// ---------------- launch ----------------
extern "C" void kernel_launch(void* const* d_in, const int* in_sizes, int n_in,
                              void* d_out, int out_size)
{
    const float* Hj   = (const float*)d_in[0];
    const float* Hi   = (const float*)d_in[1];
    const float* Wpj  = (const float*)d_in[2];
    const float* Wpi  = (const float*)d_in[3];
    const float* Ws1  = (const float*)d_in[4];
    const float* bs1  = (const float*)d_in[5];
    const float* ws2  = (const float*)d_in[6];
    const float* bs2  = (const float*)d_in[7];
    const float* Wv1  = (const float*)d_in[8];
    const float* bv1  = (const float*)d_in[9];
    const float* Wv2  = (const float*)d_in[10];
    const float* bv2  = (const float*)d_in[11];
    const float* alpha= (const float*)d_in[12];
    const int*   mask = (const int*)d_in[13];
    float* out = (float*)d_out;

    float *Zj, *Zi, *probs, *ctx, *mhid;
    cudaGetSymbolAddress((void**)&Zj, g_Zj);
    cudaGetSymbolAddress((void**)&Zi, g_Zi);
    cudaGetSymbolAddress((void**)&probs, g_probs);
    cudaGetSymbolAddress((void**)&ctx, g_ctx);
    cudaGetSymbolAddress((void**)&mhid, g_mhid);

    static int attr_done = 0;
    if (!attr_done) {
        cudaFuncSetAttribute(pairwise_tc1,
                             cudaFuncAttributeMaxDynamicSharedMemorySize, PW7_BYTES);
        attr_done = 1;
    }

    // Zj = H_j @ Wpj ; Zi = H_i @ Wpi   (2048 x 24, K=768), batched
    sgemm_small2<<<dim3(1, ROWS/64, 2), 256>>>(
        Hj, Wpj, Zj, nullptr, Hi, Wpi, Zi, nullptr,
        ROWS, DD, HD, HD, DD, DD);

    // fused pairwise (tjb computed in-block) + softmax -> probs
    pairwise_tc1<<<ROWS, 128, PW7_BYTES>>>(
        Zj, Zi, Ws1, bs1, ws2, bs2, mask, probs);

    // ctx = probs @ H_i   (batched 4x: 512 x 768, K=512) — split-K tf32
    gemm_tc4<0,false,false,false><<<dim3(HD/64, SEQ/64, BATCH), 256>>>(
        probs, Hi, ctx, SEQ, SEQ, HD, HD, nullptr, nullptr,
        (long)SEQ*SEQ, (long)SEQ*HD, (long)SEQ*HD, nullptr, nullptr);

    // mhid = relu([ctx|Hj|ctx*Hj] @ Wv1 + bv1)   (2048 x 768, K=2304; X fused)
    gemm_tc4<1,true,true,false><<<dim3(OO/64, ROWS/64, 1), 256>>>(
        nullptr, Wv1, mhid, XCOLS, 0, OO, OO, bv1, nullptr,
        0, 0, 0, ctx, Hj);

    // out = alpha * (mhid @ Wv2 + bv2)   (2048 x 768, K=768)
    gemm_tc4<0,true,false,true><<<dim3(HD/64, ROWS/64, 1), 256>>>(
        mhid, Wv2, out, OO, OO, HD, HD, bv2, alpha,
        0, 0, 0, nullptr, nullptr);
}

// round 17
// speedup vs baseline: 4.7385x; 1.3650x over previous
#include <cuda_runtime.h>
#include <cuda_fp16.h>
#include <math.h>

#define BATCH 4
#define SEQ   512
#define HD    768
#define DD    24
#define MMDIM 96
#define OO    768
#define ROWS  (BATCH*SEQ)       // 2048
#define XCOLS (3*HD)            // 2304

typedef unsigned int uint;

// ---------------- scratch (no allocations allowed) ----------------
__device__ float g_Zj[ROWS*DD];
__device__ float g_Zi[ROWS*DD];
__device__ float g_probs[(long)BATCH*SEQ*SEQ];
__device__ float g_ctx[(long)ROWS*HD];
__device__ float g_mhid[(long)ROWS*OO];

// ---------------- fp16 helpers ----------------
__device__ __forceinline__ uint pkh2(float lo, float hi) {
    half2 h = __floats2half2_rn(lo, hi);   // .x = lo (even k), .y = hi (odd k)
    return *(uint*)&h;
}
__device__ __forceinline__ void mma_f16(float* c, const uint* a, const uint* b) {
    asm volatile(
        "mma.sync.aligned.m16n8k16.row.col.f32.f16.f16.f32 "
        "{%0,%1,%2,%3}, {%4,%5,%6,%7}, {%8,%9}, {%0,%1,%2,%3};"
        : "+f"(c[0]), "+f"(c[1]), "+f"(c[2]), "+f"(c[3])
        : "r"(a[0]), "r"(a[1]), "r"(a[2]), "r"(a[3]), "r"(b[0]), "r"(b[1]));
}

// ---------------- small generic SGEMM, z-batched over pointer pairs ----------------
__global__ __launch_bounds__(256)
void sgemm_small2(const float* __restrict__ A0, const float* __restrict__ B0,
                  float* __restrict__ C0, const float* __restrict__ bias0,
                  const float* __restrict__ A1, const float* __restrict__ B1,
                  float* __restrict__ C1, const float* __restrict__ bias1,
                  int M, int N, int K, int lda, int ldb, int ldc)
{
    __shared__ float As[16][64];
    __shared__ float Bs[16][64];
    const float* A = blockIdx.z ? A1 : A0;
    const float* B = blockIdx.z ? B1 : B0;
    float*       C = blockIdx.z ? C1 : C0;
    const float* bias = blockIdx.z ? bias1 : bias0;

    const int tid = threadIdx.x;
    const int tx = tid & 15, ty = tid >> 4;
    const int row0 = blockIdx.y * 64;
    const int col0 = blockIdx.x * 64;

    float acc[4][4] = {};
    for (int k0 = 0; k0 < K; k0 += 16) {
        #pragma unroll
        for (int u = 0; u < 4; ++u) {
            int t = tid + u * 256;
            int r = t >> 4, kk = t & 15;
            int gr = row0 + r, gk = k0 + kk;
            float v = 0.f;
            if (gr < M && gk < K) v = A[(long)gr * lda + gk];
            As[kk][r] = v;
        }
        #pragma unroll
        for (int u = 0; u < 4; ++u) {
            int t = tid + u * 256;
            int kk = t >> 6, n = t & 63;
            int gk = k0 + kk, gn = col0 + n;
            float v = 0.f;
            if (gk < K && gn < N) v = B[(long)gk * ldb + gn];
            Bs[kk][n] = v;
        }
        __syncthreads();
        #pragma unroll
        for (int kk = 0; kk < 16; ++kk) {
            float4 a4 = *(const float4*)&As[kk][ty * 4];
            float4 b4 = *(const float4*)&Bs[kk][tx * 4];
            float a[4] = {a4.x, a4.y, a4.z, a4.w};
            float b[4] = {b4.x, b4.y, b4.z, b4.w};
            #pragma unroll
            for (int i = 0; i < 4; ++i)
                #pragma unroll
                for (int j = 0; j < 4; ++j)
                    acc[i][j] = fmaf(a[i], b[j], acc[i][j]);
        }
        __syncthreads();
    }
    #pragma unroll
    for (int i = 0; i < 4; ++i) {
        int r = row0 + ty * 4 + i;
        if (r >= M) continue;
        #pragma unroll
        for (int j = 0; j < 4; ++j) {
            int c = col0 + tx * 4 + j;
            if (c >= N) continue;
            float v = acc[i][j];
            if (bias) v += bias[c];
            C[(long)r * ldc + c] = v;
        }
    }
}

// ---------------- gemm_h: 64x64 tile, 256 threads, split-K x2, fp16 m16n8k16 ----------------
// 8 warps = 2 k-groups x 4 warps (2x2 grid, warp tile 32x32). ktile=32 = one k16
// slice per kg. Smem holds k-paired half2 words: As stride 20, Bs stride 72
// (all fragment LDS patterns 32-distinct-bank). Double-buffered, K % 32 == 0.
// AMODE 0: plain A. AMODE 1: A = [ctx | Hj | ctx*Hj] generated on the fly.
template<int AMODE, bool BIAS, bool RELU, bool SCALE>
__global__ __launch_bounds__(256)
void gemm_h(const float* __restrict__ A, const float* __restrict__ B,
            float* __restrict__ C, int K, int lda, int ldb, int ldc,
            const float* __restrict__ bias, const float* __restrict__ alpha_ptr,
            long sA, long sB, long sC,
            const float* __restrict__ Actx, const float* __restrict__ Ahj)
{
    __shared__ uint As[2][64][20];    // [buf][row][k2]  (10.2 KB)
    __shared__ uint Bs[2][16][72];    // [buf][k2][n]    ( 9.2 KB)
    __shared__ float redS[4096];      // cross-kg reduction (16 KB)

    const int bz = blockIdx.z;
    if (AMODE == 0) A += (long)bz * sA;
    B += (long)bz * sB;  C += (long)bz * sC;

    const int tid = threadIdx.x;
    const int wid = tid >> 5, lane = tid & 31;
    const int kg = wid >> 2;
    const int w4 = wid & 3;
    const int wm = w4 & 1, wn = w4 >> 1;
    const int g = lane >> 2, tig = lane & 3;
    const int row0 = blockIdx.y * 64;
    const int col0 = blockIdx.x * 64;

    const int ar = tid >> 2, akc = tid & 3;     // A: 64 rows x 4 k-chunks(8k)
    const int bk2 = tid >> 4, bn4 = tid & 15;   // B: 16 k2-rows x 16 n-chunks

    float acc[2][4][4];
    #pragma unroll
    for (int mt = 0; mt < 2; ++mt)
        #pragma unroll
        for (int nt = 0; nt < 4; ++nt)
            #pragma unroll
            for (int i = 0; i < 4; ++i) acc[mt][nt][i] = 0.f;

    uint4 pa, pb;

    auto fetchA = [&](int r, int gk) -> float4 {
        if (AMODE == 0) {
            return *(const float4*)&A[(long)r * lda + gk];
        } else {
            long ridx = (long)r * HD;
            if (gk < HD) {
                return *(const float4*)&Actx[ridx + gk];
            } else if (gk < 2 * HD) {
                return *(const float4*)&Ahj[ridx + gk - HD];
            } else {
                float4 c4 = *(const float4*)&Actx[ridx + gk - 2 * HD];
                float4 h4 = *(const float4*)&Ahj[ridx + gk - 2 * HD];
                return make_float4(c4.x * h4.x, c4.y * h4.y, c4.z * h4.z, c4.w * h4.w);
            }
        }
    };
    auto loadA = [&](int kt) {
        int gk = kt + akc * 8;
        float4 v0 = fetchA(row0 + ar, gk);
        float4 v1 = fetchA(row0 + ar, gk + 4);
        pa.x = pkh2(v0.x, v0.y); pa.y = pkh2(v0.z, v0.w);
        pa.z = pkh2(v1.x, v1.y); pa.w = pkh2(v1.z, v1.w);
    };
    auto loadB = [&](int kt) {
        int kr = kt + 2 * bk2;
        float4 v0 = *(const float4*)&B[(long)kr * ldb + col0 + bn4 * 4];
        float4 v1 = *(const float4*)&B[(long)(kr + 1) * ldb + col0 + bn4 * 4];
        pb.x = pkh2(v0.x, v1.x); pb.y = pkh2(v0.y, v1.y);
        pb.z = pkh2(v0.z, v1.z); pb.w = pkh2(v0.w, v1.w);
    };
    auto storeT = [&](int buf) {
        *(uint4*)&As[buf][ar][akc * 4] = pa;
        *(uint4*)&Bs[buf][bk2][bn4 * 4] = pb;
    };

    loadA(0); loadB(0);
    storeT(0);
    __syncthreads();

    int cur = 0;
    for (int kt = 0; kt < K; kt += 32) {
        const bool more = (kt + 32) < K;
        if (more) { loadA(kt + 32); loadB(kt + 32); }

        const int kb2 = kg * 8;
        uint a[2][4], b[4][2];
        #pragma unroll
        for (int mt = 0; mt < 2; ++mt) {
            int r = wm * 32 + mt * 16 + g;
            a[mt][0] = As[cur][r][kb2 + tig];
            a[mt][1] = As[cur][r + 8][kb2 + tig];
            a[mt][2] = As[cur][r][kb2 + tig + 4];
            a[mt][3] = As[cur][r + 8][kb2 + tig + 4];
        }
        #pragma unroll
        for (int nt = 0; nt < 4; ++nt) {
            int n = wn * 32 + nt * 8 + g;
            b[nt][0] = Bs[cur][kb2 + tig][n];
            b[nt][1] = Bs[cur][kb2 + tig + 4][n];
        }
        #pragma unroll
        for (int nt = 0; nt < 4; ++nt) {
            mma_f16(acc[0][nt], a[0], b[nt]);
            mma_f16(acc[1][nt], a[1], b[nt]);
        }

        if (more) storeT(cur ^ 1);
        __syncthreads();
        if (more) cur ^= 1;
    }

    // ---- cross-kg reduction ----
    const int lt = tid & 127;
    if (kg == 1) {
        #pragma unroll
        for (int mt = 0; mt < 2; ++mt)
            #pragma unroll
            for (int nt = 0; nt < 4; ++nt)
                #pragma unroll
                for (int i = 0; i < 4; ++i)
                    redS[((mt * 4 + nt) * 4 + i) * 128 + lt] = acc[mt][nt][i];
    }
    __syncthreads();
    if (kg != 0) return;
    #pragma unroll
    for (int mt = 0; mt < 2; ++mt)
        #pragma unroll
        for (int nt = 0; nt < 4; ++nt)
            #pragma unroll
            for (int i = 0; i < 4; ++i)
                acc[mt][nt][i] += redS[((mt * 4 + nt) * 4 + i) * 128 + lt];

    float alpha = 1.f;
    if (SCALE) alpha = *alpha_ptr;

    #pragma unroll
    for (int mt = 0; mt < 2; ++mt) {
        int r = row0 + wm * 32 + mt * 16 + g;
        #pragma unroll
        for (int nt = 0; nt < 4; ++nt) {
            int c = col0 + wn * 32 + nt * 8 + 2 * tig;
            float b0 = 0.f, b1 = 0.f;
            if (BIAS) { b0 = bias[c]; b1 = bias[c + 1]; }
            float v0 = acc[mt][nt][0] + b0;
            float v1 = acc[mt][nt][1] + b1;
            float v2 = acc[mt][nt][2] + b0;
            float v3 = acc[mt][nt][3] + b1;
            if (RELU) {
                v0 = fmaxf(v0, 0.f); v1 = fmaxf(v1, 0.f);
                v2 = fmaxf(v2, 0.f); v3 = fmaxf(v3, 0.f);
            }
            v0 *= alpha; v1 *= alpha; v2 *= alpha; v3 *= alpha;
            *(float2*)&C[(long)r * ldc + c] = make_float2(v0, v1);
            *(float2*)&C[(long)(r + 8) * ldc + c] = make_float2(v2, v3);
        }
    }
}

// ---------------- pairwise v8: single-pass fp16 m16n8k16 ----------------
// One block per p (128 thr, 4 warps). W = folded [W'|W1d] k-paired half2
// (stride 104); G per 128-q tile k-paired half2 (stride 28). K=48 = 3 k16 slices.
// tjb computed in-block. Static smem (~27 KB).
__global__ __launch_bounds__(128)
void pairwise_h(const float* __restrict__ Zj, const float* __restrict__ Zi,
                const float* __restrict__ Ws1, const float* __restrict__ bs1,
                const float* __restrict__ ws2,
                const float* __restrict__ bs2, const int* __restrict__ attn_mask,
                float* __restrict__ probs)
{
    __shared__ uint  Wh[24 * 104];     // [k2][m], k2 0..11 = W' pairs, 12..23 = W1d pairs
    __shared__ uint  Gs[128 * 28];     // [q][k2]
    __shared__ float logits_s[512];
    __shared__ float tjb_s[96];
    __shared__ float ws2_s[96];
    __shared__ float Zjp_s[24];
    __shared__ float red_s[8];

    const int tid = threadIdx.x;
    const int wid = tid >> 5, lane = tid & 31;
    const int g = lane >> 2, tig = lane & 3;
    const int pg = blockIdx.x;
    const int b = pg >> 9;

    if (tid < 24) Zjp_s[tid] = Zj[pg * 24 + tid];
    if (tid < 96) ws2_s[tid] = ws2[tid];
    __syncthreads();

    // tjb[m] = bs1[m] + Zjp . W1j[:,m]
    if (tid < 96) {
        float s = bs1[tid];
        #pragma unroll
        for (int d = 0; d < 24; ++d)
            s = fmaf(Zjp_s[d], Ws1[d * 96 + tid], s);
        tjb_s[tid] = s;
    }

    // Folded weights, k-paired fp16.
    for (int idx = tid; idx < 12 * 96; idx += 128) {
        int d2 = idx / 96, m = idx - d2 * 96;
        int d0 = 2 * d2, d1 = d0 + 1;
        float wp0 = fmaf(Zjp_s[d0], Ws1[(48 + d0) * 96 + m], Ws1[(24 + d0) * 96 + m]);
        float wp1 = fmaf(Zjp_s[d1], Ws1[(48 + d1) * 96 + m], Ws1[(24 + d1) * 96 + m]);
        Wh[d2 * 104 + m] = pkh2(wp0, wp1);
        Wh[(12 + d2) * 104 + m] = pkh2(Ws1[(72 + d0) * 96 + m], Ws1[(72 + d1) * 96 + m]);
    }
    __syncthreads();

    #pragma unroll 1
    for (int qt = 0; qt < 4; ++qt) {
        const int q0 = qt * 128;

        // Build G (one thread per q row): k2 0..11 = Zi pairs, 12..23 = |diff| pairs.
        {
            const int q = tid;
            const float* zrow = &Zi[((long)(b * 512 + q0 + q)) * 24];
            float4 z4[6];
            #pragma unroll
            for (int u = 0; u < 6; ++u) z4[u] = *(const float4*)&zrow[u * 4];
            float zv[24] = {z4[0].x, z4[0].y, z4[0].z, z4[0].w,
                            z4[1].x, z4[1].y, z4[1].z, z4[1].w,
                            z4[2].x, z4[2].y, z4[2].z, z4[2].w,
                            z4[3].x, z4[3].y, z4[3].z, z4[3].w,
                            z4[4].x, z4[4].y, z4[4].z, z4[4].w,
                            z4[5].x, z4[5].y, z4[5].z, z4[5].w};
            uint* dst = &Gs[q * 28];
            #pragma unroll
            for (int j = 0; j < 12; ++j)
                dst[j] = pkh2(zv[2 * j], zv[2 * j + 1]);
            #pragma unroll
            for (int j = 0; j < 12; ++j)
                dst[12 + j] = pkh2(fabsf(Zjp_s[2 * j] - zv[2 * j]),
                                   fabsf(Zjp_s[2 * j + 1] - zv[2 * j + 1]));
        }
        __syncthreads();

        float acc[2][12][4];
        #pragma unroll
        for (int mt = 0; mt < 2; ++mt)
            #pragma unroll
            for (int nt = 0; nt < 12; ++nt)
                #pragma unroll
                for (int i = 0; i < 4; ++i) acc[mt][nt][i] = 0.f;

        #pragma unroll
        for (int ks = 0; ks < 3; ++ks) {
            uint a[2][4];
            #pragma unroll
            for (int mt = 0; mt < 2; ++mt) {
                int r = wid * 32 + mt * 16 + g;
                a[mt][0] = Gs[r * 28 + ks * 8 + tig];
                a[mt][1] = Gs[(r + 8) * 28 + ks * 8 + tig];
                a[mt][2] = Gs[r * 28 + ks * 8 + tig + 4];
                a[mt][3] = Gs[(r + 8) * 28 + ks * 8 + tig + 4];
            }
            #pragma unroll
            for (int nt = 0; nt < 12; ++nt) {
                uint bb[2];
                bb[0] = Wh[(ks * 8 + tig) * 104 + nt * 8 + g];
                bb[1] = Wh[(ks * 8 + tig + 4) * 104 + nt * 8 + g];
                mma_f16(acc[0][nt], a[0], bb);
                mma_f16(acc[1][nt], a[1], bb);
            }
        }

        // epilogue: relu(acc + tjb) . ws2, reduce over the 4 tig lanes
        #pragma unroll
        for (int mt = 0; mt < 2; ++mt) {
            float s0 = 0.f, s1 = 0.f;
            #pragma unroll
            for (int nt = 0; nt < 12; ++nt) {
                int m = nt * 8 + 2 * tig;
                float t0 = tjb_s[m], t1 = tjb_s[m + 1];
                float w0 = ws2_s[m], w1 = ws2_s[m + 1];
                s0 = fmaf(fmaxf(acc[mt][nt][0] + t0, 0.f), w0, s0);
                s0 = fmaf(fmaxf(acc[mt][nt][1] + t1, 0.f), w1, s0);
                s1 = fmaf(fmaxf(acc[mt][nt][2] + t0, 0.f), w0, s1);
                s1 = fmaf(fmaxf(acc[mt][nt][3] + t1, 0.f), w1, s1);
            }
            s0 += __shfl_xor_sync(0xffffffffu, s0, 1);
            s0 += __shfl_xor_sync(0xffffffffu, s0, 2);
            s1 += __shfl_xor_sync(0xffffffffu, s1, 1);
            s1 += __shfl_xor_sync(0xffffffffu, s1, 2);
            if (tig == 0) {
                int q = q0 + wid * 32 + mt * 16 + g;
                logits_s[q] = s0;
                logits_s[q + 8] = s1;
            }
        }
        __syncthreads();
    }

    // mask + bs2
    const float bs2v = *bs2;
    #pragma unroll
    for (int q = tid; q < 512; q += 128) {
        float mv = (float)attn_mask[b * 512 + q];
        logits_s[q] += bs2v + (1.f - mv) * (-3.402823466e38f);
    }
    __syncthreads();

    // softmax over 512
    float lmax = -INFINITY;
    #pragma unroll
    for (int q = tid; q < 512; q += 128) lmax = fmaxf(lmax, logits_s[q]);
    #pragma unroll
    for (int o = 16; o > 0; o >>= 1) lmax = fmaxf(lmax, __shfl_xor_sync(0xffffffffu, lmax, o));
    if (lane == 0) red_s[wid] = lmax;
    __syncthreads();
    lmax = fmaxf(fmaxf(red_s[0], red_s[1]), fmaxf(red_s[2], red_s[3]));

    float lsum = 0.f;
    float ev[4];
    #pragma unroll
    for (int u = 0; u < 4; ++u) {
        int q = tid + u * 128;
        ev[u] = expf(logits_s[q] - lmax);
        lsum += ev[u];
    }
    #pragma unroll
    for (int o = 16; o > 0; o >>= 1) lsum += __shfl_xor_sync(0xffffffffu, lsum, o);
    if (lane == 0) red_s[4 + wid] = lsum;
    __syncthreads();
    const float inv = 1.f / (red_s[4] + red_s[5] + red_s[6] + red_s[7]);
    #pragma unroll
    for (int u = 0; u < 4; ++u) {
        int q = tid + u * 128;
        probs[(long)pg * 512 + q] = ev[u] * inv;
    }
}

// ---------------- launch ----------------
extern "C" void kernel_launch(void* const* d_in, const int* in_sizes, int n_in,
                              void* d_out, int out_size)
{
    const float* Hj   = (const float*)d_in[0];
    const float* Hi   = (const float*)d_in[1];
    const float* Wpj  = (const float*)d_in[2];
    const float* Wpi  = (const float*)d_in[3];
    const float* Ws1  = (const float*)d_in[4];
    const float* bs1  = (const float*)d_in[5];
    const float* ws2  = (const float*)d_in[6];
    const float* bs2  = (const float*)d_in[7];
    const float* Wv1  = (const float*)d_in[8];
    const float* bv1  = (const float*)d_in[9];
    const float* Wv2  = (const float*)d_in[10];
    const float* bv2  = (const float*)d_in[11];
    const float* alpha= (const float*)d_in[12];
    const int*   mask = (const int*)d_in[13];
    float* out = (float*)d_out;

    float *Zj, *Zi, *probs, *ctx, *mhid;
    cudaGetSymbolAddress((void**)&Zj, g_Zj);
    cudaGetSymbolAddress((void**)&Zi, g_Zi);
    cudaGetSymbolAddress((void**)&probs, g_probs);
    cudaGetSymbolAddress((void**)&ctx, g_ctx);
    cudaGetSymbolAddress((void**)&mhid, g_mhid);

    // Zj = H_j @ Wpj ; Zi = H_i @ Wpi   (2048 x 24, K=768), batched
    sgemm_small2<<<dim3(1, ROWS/64, 2), 256>>>(
        Hj, Wpj, Zj, nullptr, Hi, Wpi, Zi, nullptr,
        ROWS, DD, HD, HD, DD, DD);

    // fused pairwise (fp16 mma) + softmax -> probs
    pairwise_h<<<ROWS, 128>>>(
        Zj, Zi, Ws1, bs1, ws2, bs2, mask, probs);

    // ctx = probs @ H_i   (batched 4x: 512 x 768, K=512)
    gemm_h<0,false,false,false><<<dim3(HD/64, SEQ/64, BATCH), 256>>>(
        probs, Hi, ctx, SEQ, SEQ, HD, HD, nullptr, nullptr,
        (long)SEQ*SEQ, (long)SEQ*HD, (long)SEQ*HD, nullptr, nullptr);

    // mhid = relu([ctx|Hj|ctx*Hj] @ Wv1 + bv1)   (2048 x 768, K=2304; X fused)
    gemm_h<1,true,true,false><<<dim3(OO/64, ROWS/64, 1), 256>>>(
        nullptr, Wv1, mhid, XCOLS, 0, OO, OO, bv1, nullptr,
        0, 0, 0, ctx, Hj);

    // out = alpha * (mhid @ Wv2 + bv2)   (2048 x 768, K=768)
    gemm_h<0,true,false,true><<<dim3(HD/64, ROWS/64, 1), 256>>>(
        mhid, Wv2, out, OO, OO, HD, HD, bv2, alpha,
        0, 0, 0, nullptr, nullptr);
}